// round 11
// baseline (speedup 1.0000x reference)
#include <cuda_runtime.h>
#include <math.h>

// Problem constants
#define NTOK 1024      // B*S
#define DMODEL 1024
#define NH 16
#define HDIM 64
#define SEQ 256
#define NB 4
#define NE 8
#define DHID 2048
#define MAXM 1024      // max rows per expert

// ---------------- scratch (device globals; no allocation allowed) ----------------
__device__ float g_feat[NTOK * DMODEL];
__device__ float g_xn[NTOK * DMODEL];     // exact LN output (route reads this)
__device__ float g_xnr[NTOK * DMODEL];    // tf32-rounded LN output (GEMM A)
__device__ float g_q[NTOK * DMODEL];
__device__ float g_k[NTOK * DMODEL];
__device__ float g_v[NTOK * DMODEL];
__device__ float g_o[NTOK * DMODEL];
__device__ float g_h[NE * MAXM * DHID];    // expert hidden (tf32-rounded)
__device__ float g_y2[NE * MAXM * DMODEL]; // expert output
__device__ int   g_cnt[NE];
__device__ int   g_ptok[NE * MAXM];
__device__ int   g_pos[NTOK * 2];
__device__ float g_wgt[NTOK * 2];

__device__ __forceinline__ unsigned f2tf(float f) {
    unsigned u; asm("cvt.rna.tf32.f32 %0, %1;" : "=r"(u) : "f"(f)); return u;
}
__device__ __forceinline__ float roundtf(float f) {
    return __uint_as_float(f2tf(f));
}
__device__ __forceinline__ void cpa16(float* dst_smem, const float* src) {
    unsigned d = (unsigned)__cvta_generic_to_shared(dst_smem);
    asm volatile("cp.async.cg.shared.global [%0], [%1], 16;\n" :: "r"(d), "l"(src));
}
__device__ __forceinline__ void cp_commit() {
    asm volatile("cp.async.commit_group;\n" ::: "memory");
}
template<int N>
__device__ __forceinline__ void cp_wait() {
    asm volatile("cp.async.wait_group %0;\n" :: "n"(N) : "memory");
}

// ---------------- embedding ----------------
__global__ void embed_kernel(const int* __restrict__ et, const int* __restrict__ xi,
                             const float* __restrict__ ent, const float* __restrict__ maskemb,
                             const float* __restrict__ rel, const float* __restrict__ type)
{
    int tok = blockIdx.x, t = threadIdx.x;   // 256 threads, 1 float4 each
    int ty = et[tok];
    int xv = xi[tok];
    const float* src;
    if (ty == 0)      src = ent + (size_t)(((unsigned)xv) % 40000u) * DMODEL;
    else if (ty == 1) src = maskemb;
    else              src = rel + (size_t)(((unsigned)xv) % 1000u) * DMODEL;
    float4 s4 = ((const float4*)src)[t];
    float4 t4 = ((const float4*)(type + (size_t)ty * DMODEL))[t];
    float4 r = make_float4(s4.x + t4.x, s4.y + t4.y, s4.z + t4.z, s4.w + t4.w);
    ((float4*)(g_feat + (size_t)tok * DMODEL))[t] = r;
}

// ---------------- layernorm: writes exact y and tf32-rounded yr ----------------
__global__ void ln_kernel(const float* __restrict__ x, const float* __restrict__ g,
                          const float* __restrict__ b, float* __restrict__ y,
                          float* __restrict__ yr)
{
    __shared__ float red[256];
    int row = blockIdx.x, t = threadIdx.x;
    float4 xv = ((const float4*)(x + (size_t)row * DMODEL))[t];
    red[t] = xv.x + xv.y + xv.z + xv.w;
    __syncthreads();
    #pragma unroll
    for (int off = 128; off > 0; off >>= 1) { if (t < off) red[t] += red[t + off]; __syncthreads(); }
    float m = red[0] * (1.0f / DMODEL);
    __syncthreads();
    float dx = xv.x - m, dy = xv.y - m, dz = xv.z - m, dw = xv.w - m;
    red[t] = dx * dx + dy * dy + dz * dz + dw * dw;
    __syncthreads();
    #pragma unroll
    for (int off = 128; off > 0; off >>= 1) { if (t < off) red[t] += red[t + off]; __syncthreads(); }
    float rs = rsqrtf(red[0] * (1.0f / DMODEL) + 1e-5f);
    float4 gv = ((const float4*)g)[t];
    float4 bv = ((const float4*)b)[t];
    float4 o = make_float4(dx * rs * gv.x + bv.x, dy * rs * gv.y + bv.y,
                           dz * rs * gv.z + bv.z, dw * rs * gv.w + bv.w);
    ((float4*)(y + (size_t)row * DMODEL))[t] = o;
    float4 orr = make_float4(roundtf(o.x), roundtf(o.y), roundtf(o.z), roundtf(o.w));
    ((float4*)(yr + (size_t)row * DMODEL))[t] = orr;
}

// ---------------- TF32 tensor-core GEMM, 5-stage cp.async pipeline ----------------
// A is PRE-ROUNDED to tf32 (RNA) by its producer; copied raw.
// B copied raw fp32; converted to tf32 (RNA) after fragment load.
#define LDA 20
#define LDB 72
#define TG_STAGES 5
#define A_ST (128 * LDA)
#define B_ST (16 * LDB)
#define ST_FLOATS (A_ST + B_ST)
#define TG_SMEM (TG_STAGES * ST_FLOATS * 4)

template<int RELU, int ACCUM, int EXPERT, int GATHER, int QKV>
__global__ void __launch_bounds__(256)
tgemm(const float* __restrict__ A,
      const float* __restrict__ W0, const float* __restrict__ Wx1, const float* __restrict__ Wx2,
      const float* __restrict__ B0, const float* __restrict__ Bx1, const float* __restrict__ Bx2,
      float* __restrict__ C0, float* __restrict__ Cx1, float* __restrict__ Cx2,
      int M, int N, int K,
      const int* __restrict__ gather, const int* __restrict__ cnt,
      size_t aStride, size_t cStride)
{
    extern __shared__ float dynsm[];

    int e = EXPERT ? blockIdx.z : 0;
    int Mloc = EXPERT ? cnt[e] : M;
    int mBase = blockIdx.y * 128;
    if (mBase >= Mloc) return;
    int nBase = blockIdx.x * 64;

    const float* W = W0; const float* bias = B0; float* C = C0;
    if (QKV) {
        int z = blockIdx.z;
        if (z == 1)      { W = Wx1; bias = Bx1; C = Cx1; }
        else if (z == 2) { W = Wx2; bias = Bx2; C = Cx2; }
    }
    const float* Ap = A;
    if (EXPERT) {
        W = W0 + (size_t)e * K * N;
        bias = B0 + (size_t)e * N;
        C = C0 + (size_t)e * cStride;
        if (!GATHER) Ap = A + (size_t)e * aStride;
    }

    int tid = threadIdx.x;
    int lane = tid & 31, warp = tid >> 5;
    int wM = (warp & 1) * 64;
    int wN = (warp >> 1) * 16;
    int g = lane >> 2, t = lane & 3;

    // A staging: two rows per thread, one 16B chunk along k each
    int r0 = tid >> 2;
    int r1 = r0 + 64;
    int ac4 = (tid & 3) * 4;
    int m0 = mBase + r0; m0 = m0 < Mloc ? m0 : Mloc - 1;
    int m1 = mBase + r1; m1 = m1 < Mloc ? m1 : Mloc - 1;
    int ar0 = GATHER ? gather[e * MAXM + m0] : m0;
    int ar1 = GATHER ? gather[e * MAXM + m1] : m1;
    const float* pA0 = Ap + (size_t)ar0 * K + ac4;
    const float* pA1 = Ap + (size_t)ar1 * K + ac4;

    // B staging: 16 x 64 tile, one 16B chunk per thread
    int br  = tid >> 4;
    int bc4 = (tid & 15) * 4;
    const float* pB = W + (size_t)br * N + nBase + bc4;

    float acc[4][2][4];
    #pragma unroll
    for (int i = 0; i < 4; i++)
        #pragma unroll
        for (int j = 0; j < 2; j++)
            #pragma unroll
            for (int q = 0; q < 4; q++) acc[i][j][q] = 0.0f;

    const int KI = K >> 4;

    // prologue: prefetch stages 0..TG_STAGES-2
    #pragma unroll
    for (int s = 0; s < TG_STAGES - 1; s++) {
        float* As_ = dynsm + s * ST_FLOATS;
        float* Bs_ = As_ + A_ST;
        int k = s * 16;
        if (k < K) {
            cpa16(As_ + r0 * LDA + ac4, pA0 + k);
            cpa16(As_ + r1 * LDA + ac4, pA1 + k);
            cpa16(Bs_ + br * LDB + bc4, pB + (size_t)k * N);
        }
        cp_commit();
    }

    int slot = 0, pslot = TG_STAGES - 1;
    for (int i = 0; i < KI; i++) {
        cp_wait<TG_STAGES - 2>();
        __syncthreads();

        // prefetch into the slot freed by iteration i-1
        {
            int k = (i + TG_STAGES - 1) * 16;
            if (k < K) {
                float* As_ = dynsm + pslot * ST_FLOATS;
                float* Bs_ = As_ + A_ST;
                cpa16(As_ + r0 * LDA + ac4, pA0 + k);
                cpa16(As_ + r1 * LDA + ac4, pA1 + k);
                cpa16(Bs_ + br * LDB + bc4, pB + (size_t)k * N);
            }
            cp_commit();
            if (++pslot == TG_STAGES) pslot = 0;
        }

        const float* As_ = dynsm + slot * ST_FLOATS;
        const float* Bs_ = As_ + A_ST;
        if (++slot == TG_STAGES) slot = 0;

        #pragma unroll
        for (int ks = 0; ks < 2; ks++) {
            unsigned af[4][4], bf[2][2];
            #pragma unroll
            for (int mt = 0; mt < 4; mt++) {
                int base = (wM + mt * 16 + g) * LDA + ks * 8 + t;
                af[mt][0] = __float_as_uint(As_[base]);
                af[mt][1] = __float_as_uint(As_[base + 8 * LDA]);
                af[mt][2] = __float_as_uint(As_[base + 4]);
                af[mt][3] = __float_as_uint(As_[base + 8 * LDA + 4]);
            }
            #pragma unroll
            for (int nt = 0; nt < 2; nt++) {
                int base = (ks * 8 + t) * LDB + wN + nt * 8 + g;
                bf[nt][0] = f2tf(Bs_[base]);
                bf[nt][1] = f2tf(Bs_[base + 4 * LDB]);
            }
            #pragma unroll
            for (int mt = 0; mt < 4; mt++)
                #pragma unroll
                for (int nt = 0; nt < 2; nt++)
                    asm volatile(
                        "mma.sync.aligned.m16n8k8.row.col.f32.tf32.tf32.f32 "
                        "{%0,%1,%2,%3}, {%4,%5,%6,%7}, {%8,%9}, {%0,%1,%2,%3};"
                        : "+f"(acc[mt][nt][0]), "+f"(acc[mt][nt][1]),
                          "+f"(acc[mt][nt][2]), "+f"(acc[mt][nt][3])
                        : "r"(af[mt][0]), "r"(af[mt][1]), "r"(af[mt][2]), "r"(af[mt][3]),
                          "r"(bf[nt][0]), "r"(bf[nt][1]));
        }
    }

    #pragma unroll
    for (int mt = 0; mt < 4; mt++) {
        #pragma unroll
        for (int half = 0; half < 2; half++) {
            int r = mBase + wM + mt * 16 + g + half * 8;
            if (r < Mloc) {
                #pragma unroll
                for (int nt = 0; nt < 2; nt++) {
                    int col = nBase + wN + nt * 8 + 2 * t;
                    float* cp = C + (size_t)r * N + col;
                    float v0 = acc[mt][nt][half * 2 + 0] + bias[col];
                    float v1 = acc[mt][nt][half * 2 + 1] + bias[col + 1];
                    if (RELU) {
                        v0 = roundtf(fmaxf(v0, 0.0f));
                        v1 = roundtf(fmaxf(v1, 0.0f));
                    }
                    if (ACCUM) { cp[0] += v0; cp[1] += v1; }
                    else       { cp[0] = v0;  cp[1] = v1; }
                }
            }
        }
    }
}

// ---------------- tiled attention ----------------
#define QT 32
#define KT 64
#define KVP 68                 // K/V smem row pitch (floats)
#define SCP 260                // score row pitch (floats, mult of 4)
#define ATTN_SMEM ((QT*KVP + KT*KVP + QT*SCP) * 4)

__global__ void __launch_bounds__(256)
attn2_kernel(const float* __restrict__ q, const float* __restrict__ k,
             const float* __restrict__ v, const int* __restrict__ abt,
             const float* __restrict__ bias_emb, float* __restrict__ o)
{
    extern __shared__ float sm[];
    float* Qs  = sm;                 // [QT][KVP]
    float* KVs = sm + QT * KVP;      // [KT][KVP]
    float* Sc  = KVs + KT * KVP;     // [QT][SCP]

    int bid = blockIdx.x;
    int qt = bid & 7, h = (bid >> 3) & 15, b = bid >> 7;
    int q0 = qt * QT;
    int t = threadIdx.x;
    int lane = t & 31, warp = t >> 5;

    // load Q tile (scaled by 1/8)
    {
        int r = t >> 3, c = (t & 7) * 8;
        const float* qg = q + (size_t)(b * SEQ + q0 + r) * DMODEL + h * HDIM + c;
        float4 a0 = *(const float4*)qg;
        float4 a1 = *(const float4*)(qg + 4);
        float* dst = Qs + r * KVP + c;
        dst[0] = a0.x * 0.125f; dst[1] = a0.y * 0.125f; dst[2] = a0.z * 0.125f; dst[3] = a0.w * 0.125f;
        dst[4] = a1.x * 0.125f; dst[5] = a1.y * 0.125f; dst[6] = a1.z * 0.125f; dst[7] = a1.w * 0.125f;
    }
    __syncthreads();

    int qq = t >> 3;
    int kk = t & 7;

    // -------- pass 1: scores --------
    for (int kt = 0; kt < 4; kt++) {
        int k0 = kt * KT;
        {
            int r = t >> 2, c = (t & 3) * 16;
            const float* kg = k + (size_t)(b * SEQ + k0 + r) * DMODEL + h * HDIM + c;
            float4 x0 = *(const float4*)kg;
            float4 x1 = *(const float4*)(kg + 4);
            float4 x2 = *(const float4*)(kg + 8);
            float4 x3 = *(const float4*)(kg + 12);
            float* dst = KVs + r * KVP + c;
            *(float4*)(dst)      = x0;
            *(float4*)(dst + 4)  = x1;
            *(float4*)(dst + 8)  = x2;
            *(float4*)(dst + 12) = x3;
        }
        __syncthreads();

        float acc[8] = {0, 0, 0, 0, 0, 0, 0, 0};
        #pragma unroll
        for (int d4 = 0; d4 < 16; d4++) {
            float4 qv = *(const float4*)(Qs + qq * KVP + d4 * 4);
            #pragma unroll
            for (int j = 0; j < 8; j++) {
                float4 kv = *(const float4*)(KVs + (kk + 8 * j) * KVP + d4 * 4);
                acc[j] += qv.x * kv.x + qv.y * kv.y + qv.z * kv.z + qv.w * kv.w;
            }
        }
        const int* arow = abt + (size_t)(b * SEQ + q0 + qq) * SEQ + k0;
        #pragma unroll
        for (int j = 0; j < 8; j++) {
            int bt = arow[kk + 8 * j];
            Sc[qq * SCP + k0 + kk + 8 * j] = acc[j] + bias_emb[bt * NH + h];
        }
        __syncthreads();
    }

    // -------- softmax --------
    #pragma unroll
    for (int rr = 0; rr < 4; rr++) {
        int r = warp * 4 + rr;
        float vals[8];
        float mx = -3.4e38f;
        #pragma unroll
        for (int c = 0; c < 8; c++) {
            vals[c] = Sc[r * SCP + lane + 32 * c];
            mx = fmaxf(mx, vals[c]);
        }
        #pragma unroll
        for (int off = 16; off > 0; off >>= 1)
            mx = fmaxf(mx, __shfl_xor_sync(0xffffffffu, mx, off));
        float s = 0.0f;
        #pragma unroll
        for (int c = 0; c < 8; c++) { vals[c] = expf(vals[c] - mx); s += vals[c]; }
        #pragma unroll
        for (int off = 16; off > 0; off >>= 1)
            s += __shfl_xor_sync(0xffffffffu, s, off);
        float inv = 1.0f / s;
        #pragma unroll
        for (int c = 0; c < 8; c++)
            Sc[r * SCP + lane + 32 * c] = vals[c] * inv;
    }
    __syncthreads();

    // -------- pass 2: PV --------
    int dh = t & 7;
    float4 o0 = make_float4(0, 0, 0, 0);
    float4 o1 = make_float4(0, 0, 0, 0);
    for (int kt = 0; kt < 4; kt++) {
        int k0 = kt * KT;
        {
            int r = t >> 2, c = (t & 3) * 16;
            const float* vg = v + (size_t)(b * SEQ + k0 + r) * DMODEL + h * HDIM + c;
            float4 x0 = *(const float4*)vg;
            float4 x1 = *(const float4*)(vg + 4);
            float4 x2 = *(const float4*)(vg + 8);
            float4 x3 = *(const float4*)(vg + 12);
            float* dst = KVs + r * KVP + c;
            *(float4*)(dst)      = x0;
            *(float4*)(dst + 4)  = x1;
            *(float4*)(dst + 8)  = x2;
            *(float4*)(dst + 12) = x3;
        }
        __syncthreads();

        const float* prow = Sc + qq * SCP + k0;
        #pragma unroll
        for (int j4 = 0; j4 < 16; j4++) {
            float4 p4 = *(const float4*)(prow + j4 * 4);
            float pr[4] = {p4.x, p4.y, p4.z, p4.w};
            #pragma unroll
            for (int u = 0; u < 4; u++) {
                int j = j4 * 4 + u;
                float4 va = *(const float4*)(KVs + j * KVP + dh * 4);
                float4 vb = *(const float4*)(KVs + j * KVP + (dh + 8) * 4);
                float p = pr[u];
                o0.x += p * va.x; o0.y += p * va.y; o0.z += p * va.z; o0.w += p * va.w;
                o1.x += p * vb.x; o1.y += p * vb.y; o1.z += p * vb.z; o1.w += p * vb.w;
            }
        }
        __syncthreads();
    }

    o0.x = roundtf(o0.x); o0.y = roundtf(o0.y); o0.z = roundtf(o0.z); o0.w = roundtf(o0.w);
    o1.x = roundtf(o1.x); o1.y = roundtf(o1.y); o1.z = roundtf(o1.z); o1.w = roundtf(o1.w);
    float* og = o + (size_t)(b * SEQ + q0 + qq) * DMODEL + h * HDIM;
    *(float4*)(og + dh * 4) = o0;
    *(float4*)(og + 32 + dh * 4) = o1;
}

// ---------------- MoE routing ----------------
__global__ void reset_kernel() { if (threadIdx.x < NE) g_cnt[threadIdx.x] = 0; }

__global__ void route_kernel(const float* __restrict__ z, const float* __restrict__ gw,
                             const float* __restrict__ gb)
{
    __shared__ float lg[NE];
    int tok = blockIdx.x;
    int lane = threadIdx.x & 31, e = threadIdx.x >> 5;
    const float* zr = z + (size_t)tok * DMODEL;
    float s = 0.0f;
    for (int kk = lane; kk < DMODEL; kk += 32) s += zr[kk] * gw[kk * NE + e];
    #pragma unroll
    for (int off = 16; off > 0; off >>= 1) s += __shfl_down_sync(0xffffffffu, s, off);
    if (lane == 0) lg[e] = s + gb[e];
    __syncthreads();
    if (threadIdx.x == 0) {
        int i0 = 0; float v0 = lg[0];
        #pragma unroll
        for (int i = 1; i < NE; i++) if (lg[i] > v0) { v0 = lg[i]; i0 = i; }
        int i1 = -1; float v1 = -3.4e38f;
        #pragma unroll
        for (int i = 0; i < NE; i++) if (i != i0 && lg[i] > v1) { v1 = lg[i]; i1 = i; }
        float e1 = expf(v1 - v0);
        float invs = 1.0f / (1.0f + e1);
        float w0 = invs, w1 = e1 * invs;
        int p0 = atomicAdd(&g_cnt[i0], 1);
        g_ptok[i0 * MAXM + p0] = tok;
        g_pos[2 * tok] = i0 * MAXM + p0;
        g_wgt[2 * tok] = w0;
        int p1 = atomicAdd(&g_cnt[i1], 1);
        g_ptok[i1 * MAXM + p1] = tok;
        g_pos[2 * tok + 1] = i1 * MAXM + p1;
        g_wgt[2 * tok + 1] = w1;
    }
}

__global__ void combine_kernel()
{
    int tok = blockIdx.x, t = threadIdx.x;
    int p0 = g_pos[2 * tok], p1 = g_pos[2 * tok + 1];
    float w0 = g_wgt[2 * tok], w1 = g_wgt[2 * tok + 1];
    float4 a = ((const float4*)(g_y2 + (size_t)p0 * DMODEL))[t];
    float4 b = ((const float4*)(g_y2 + (size_t)p1 * DMODEL))[t];
    float4* f = (float4*)(g_feat + (size_t)tok * DMODEL);
    float4 fv = f[t];
    fv.x += w0 * a.x + w1 * b.x;
    fv.y += w0 * a.y + w1 * b.y;
    fv.z += w0 * a.z + w1 * b.z;
    fv.w += w0 * a.w + w1 * b.w;
    f[t] = fv;
}

// ---------------- host orchestration ----------------
extern "C" void kernel_launch(void* const* d_in, const int* in_sizes, int n_in,
                              void* d_out, int out_size)
{
    (void)in_sizes; (void)n_in; (void)out_size;
    const int*   et       = (const int*)d_in[0];
    const int*   xi       = (const int*)d_in[1];
    const int*   abt      = (const int*)d_in[2];
    const float* ent      = (const float*)d_in[3];
    const float* maskemb  = (const float*)d_in[4];
    const float* rel      = (const float*)d_in[5];
    const float* type     = (const float*)d_in[6];
    const float* bias_emb = (const float*)d_in[7];
    const float* ln1g     = (const float*)d_in[8];
    const float* ln1b     = (const float*)d_in[9];
    const float* wq       = (const float*)d_in[10];
    const float* bq       = (const float*)d_in[11];
    const float* wk       = (const float*)d_in[12];
    const float* bk       = (const float*)d_in[13];
    const float* wv       = (const float*)d_in[14];
    const float* bv       = (const float*)d_in[15];
    const float* wo       = (const float*)d_in[16];
    const float* bo       = (const float*)d_in[17];
    const float* ln2g     = (const float*)d_in[18];
    const float* ln2b     = (const float*)d_in[19];
    const float* gw       = (const float*)d_in[20];
    const float* gb       = (const float*)d_in[21];
    const float* w1       = (const float*)d_in[22];
    const float* b1       = (const float*)d_in[23];
    const float* w2       = (const float*)d_in[24];
    const float* b2       = (const float*)d_in[25];
    const float* flng     = (const float*)d_in[26];
    const float* flnb     = (const float*)d_in[27];
    float* out = (float*)d_out;

    float *feat, *xn, *xnr, *qb2, *kb2, *vb2, *ob, *hb, *yb;
    int *cntp, *ptokp;
    cudaGetSymbolAddress((void**)&feat,  g_feat);
    cudaGetSymbolAddress((void**)&xn,    g_xn);
    cudaGetSymbolAddress((void**)&xnr,   g_xnr);
    cudaGetSymbolAddress((void**)&qb2,   g_q);
    cudaGetSymbolAddress((void**)&kb2,   g_k);
    cudaGetSymbolAddress((void**)&vb2,   g_v);
    cudaGetSymbolAddress((void**)&ob,    g_o);
    cudaGetSymbolAddress((void**)&hb,    g_h);
    cudaGetSymbolAddress((void**)&yb,    g_y2);
    cudaGetSymbolAddress((void**)&cntp,  g_cnt);
    cudaGetSymbolAddress((void**)&ptokp, g_ptok);

    static int attr_set = 0;
    if (!attr_set) {
        cudaFuncSetAttribute(attn2_kernel,
                             cudaFuncAttributeMaxDynamicSharedMemorySize, ATTN_SMEM);
        cudaFuncSetAttribute(tgemm<0,0,0,0,1>,
                             cudaFuncAttributeMaxDynamicSharedMemorySize, TG_SMEM);
        cudaFuncSetAttribute(tgemm<0,1,0,0,0>,
                             cudaFuncAttributeMaxDynamicSharedMemorySize, TG_SMEM);
        cudaFuncSetAttribute(tgemm<1,0,1,1,0>,
                             cudaFuncAttributeMaxDynamicSharedMemorySize, TG_SMEM);
        cudaFuncSetAttribute(tgemm<0,0,1,0,0>,
                             cudaFuncAttributeMaxDynamicSharedMemorySize, TG_SMEM);
        attr_set = 1;
    }

    embed_kernel<<<NTOK, 256>>>(et, xi, ent, maskemb, rel, type);

    for (int l = 0; l < 2; l++) {
        const size_t dd = (size_t)DMODEL * DMODEL;
        // 1) LN1 -> xn + xnr (rounded, GEMM A)
        ln_kernel<<<NTOK, 256>>>(feat, ln1g + l * DMODEL, ln1b + l * DMODEL, xn, xnr);
        // 2) fused q,k,v projections
        tgemm<0,0,0,0,1><<<dim3(16, 8, 3), 256, TG_SMEM>>>(
            xnr, wq + l * dd, wk + l * dd, wv + l * dd,
            bq + l * DMODEL, bk + l * DMODEL, bv + l * DMODEL,
            qb2, kb2, vb2,
            NTOK, DMODEL, DMODEL, (const int*)0, (const int*)0, 0, 0);
        // 3) attention (tiled); output pre-rounded for wo GEMM
        attn2_kernel<<<NB * NH * (SEQ / QT), 256, ATTN_SMEM>>>(
            qb2, kb2, vb2, abt, bias_emb, ob);
        // 4) out proj + residual accumulate
        tgemm<0,1,0,0,0><<<dim3(16, 8), 256, TG_SMEM>>>(
            ob, wo + l * dd, (const float*)0, (const float*)0,
            bo + l * DMODEL, (const float*)0, (const float*)0,
            feat, (float*)0, (float*)0,
            NTOK, DMODEL, DMODEL, (const int*)0, (const int*)0, 0, 0);
        // 5) LN2 -> xn (exact, routing) + xnr (rounded, GEMM A)
        ln_kernel<<<NTOK, 256>>>(feat, ln2g + l * DMODEL, ln2b + l * DMODEL, xn, xnr);
        // 6) routing on exact xn
        reset_kernel<<<1, 32>>>();
        route_kernel<<<NTOK, 256>>>(xn, gw + (size_t)l * DMODEL * NE, gb + l * NE);
        // 7) expert up-proj + relu (gathered rows of xnr); output pre-rounded
        tgemm<1,0,1,1,0><<<dim3(32, 8, 8), 256, TG_SMEM>>>(
            xnr, w1 + (size_t)l * NE * DMODEL * DHID, (const float*)0, (const float*)0,
            b1 + (size_t)l * NE * DHID, (const float*)0, (const float*)0,
            hb, (float*)0, (float*)0,
            MAXM, DHID, DMODEL, ptokp, cntp, 0, (size_t)MAXM * DHID);
        // 8) expert down-proj
        tgemm<0,0,1,0,0><<<dim3(16, 8, 8), 256, TG_SMEM>>>(
            hb, w2 + (size_t)l * NE * DHID * DMODEL, (const float*)0, (const float*)0,
            b2 + (size_t)l * NE * DMODEL, (const float*)0, (const float*)0,
            yb, (float*)0, (float*)0,
            MAXM, DMODEL, DHID, (const int*)0, cntp, (size_t)MAXM * DHID, (size_t)MAXM * DMODEL);
        // 9) weighted combine into feat
        combine_kernel<<<NTOK, 256>>>();
    }

    // final layernorm -> out (exact); rounded copy goes to scratch
    ln_kernel<<<NTOK, 256>>>(feat, flng, flnb, out, xnr);
}

// round 12
// speedup vs baseline: 1.0599x; 1.0599x over previous
#include <cuda_runtime.h>
#include <math.h>

// Problem constants
#define NTOK 1024      // B*S
#define DMODEL 1024
#define NH 16
#define HDIM 64
#define SEQ 256
#define NB 4
#define NE 8
#define DHID 2048
#define MAXM 1024      // max rows per expert

// ---------------- scratch (device globals; no allocation allowed) ----------------
__device__ float g_feat[NTOK * DMODEL];
__device__ float g_xn[NTOK * DMODEL];     // exact LN output (route reads this)
__device__ float g_xnr[NTOK * DMODEL];    // tf32-rounded LN output (GEMM A)
__device__ float g_q[NTOK * DMODEL];
__device__ float g_k[NTOK * DMODEL];
__device__ float g_v[NTOK * DMODEL];
__device__ float g_o[NTOK * DMODEL];
__device__ float g_h[NE * MAXM * DHID];    // expert hidden (tf32-rounded)
__device__ float g_y2[NE * MAXM * DMODEL]; // expert output
__device__ int   g_cnt[NE];
__device__ int   g_ptok[NE * MAXM];
__device__ int   g_pos[NTOK * 2];
__device__ float g_wgt[NTOK * 2];

__device__ __forceinline__ unsigned f2tf(float f) {
    unsigned u; asm("cvt.rna.tf32.f32 %0, %1;" : "=r"(u) : "f"(f)); return u;
}
__device__ __forceinline__ float roundtf(float f) {
    return __uint_as_float(f2tf(f));
}

// ---------------- embedding ----------------
__global__ void embed_kernel(const int* __restrict__ et, const int* __restrict__ xi,
                             const float* __restrict__ ent, const float* __restrict__ maskemb,
                             const float* __restrict__ rel, const float* __restrict__ type)
{
    int tok = blockIdx.x, t = threadIdx.x;   // 256 threads, 1 float4 each
    int ty = et[tok];
    int xv = xi[tok];
    const float* src;
    if (ty == 0)      src = ent + (size_t)(((unsigned)xv) % 40000u) * DMODEL;
    else if (ty == 1) src = maskemb;
    else              src = rel + (size_t)(((unsigned)xv) % 1000u) * DMODEL;
    float4 s4 = ((const float4*)src)[t];
    float4 t4 = ((const float4*)(type + (size_t)ty * DMODEL))[t];
    float4 r = make_float4(s4.x + t4.x, s4.y + t4.y, s4.z + t4.z, s4.w + t4.w);
    ((float4*)(g_feat + (size_t)tok * DMODEL))[t] = r;
}

// ---------------- layernorm: writes exact y and tf32-rounded yr ----------------
// clearcnt != 0: block 0 also resets the MoE counters (folds the reset launch).
__global__ void ln_kernel(const float* __restrict__ x, const float* __restrict__ g,
                          const float* __restrict__ b, float* __restrict__ y,
                          float* __restrict__ yr, int clearcnt)
{
    __shared__ float red[256];
    int row = blockIdx.x, t = threadIdx.x;
    if (clearcnt && row == 0 && t < NE) g_cnt[t] = 0;
    float4 xv = ((const float4*)(x + (size_t)row * DMODEL))[t];
    red[t] = xv.x + xv.y + xv.z + xv.w;
    __syncthreads();
    #pragma unroll
    for (int off = 128; off > 0; off >>= 1) { if (t < off) red[t] += red[t + off]; __syncthreads(); }
    float m = red[0] * (1.0f / DMODEL);
    __syncthreads();
    float dx = xv.x - m, dy = xv.y - m, dz = xv.z - m, dw = xv.w - m;
    red[t] = dx * dx + dy * dy + dz * dz + dw * dw;
    __syncthreads();
    #pragma unroll
    for (int off = 128; off > 0; off >>= 1) { if (t < off) red[t] += red[t + off]; __syncthreads(); }
    float rs = rsqrtf(red[0] * (1.0f / DMODEL) + 1e-5f);
    float4 gv = ((const float4*)g)[t];
    float4 bv = ((const float4*)b)[t];
    float4 o = make_float4(dx * rs * gv.x + bv.x, dy * rs * gv.y + bv.y,
                           dz * rs * gv.z + bv.z, dw * rs * gv.w + bv.w);
    ((float4*)(y + (size_t)row * DMODEL))[t] = o;
    float4 orr = make_float4(roundtf(o.x), roundtf(o.y), roundtf(o.z), roundtf(o.w));
    ((float4*)(yr + (size_t)row * DMODEL))[t] = orr;
}

// ---------------- TF32 tensor-core GEMM (R9 version: static double-buffer) ----------------
// A is PRE-ROUNDED to tf32 (RNA) by its producer.
#define LDA 20
#define LDB 72

template<int RELU, int ACCUM, int EXPERT, int GATHER, int QKV>
__global__ void __launch_bounds__(256)
tgemm(const float* __restrict__ A,
      const float* __restrict__ W0, const float* __restrict__ Wx1, const float* __restrict__ Wx2,
      const float* __restrict__ B0, const float* __restrict__ Bx1, const float* __restrict__ Bx2,
      float* __restrict__ C0, float* __restrict__ Cx1, float* __restrict__ Cx2,
      int M, int N, int K,
      const int* __restrict__ gather, const int* __restrict__ cnt,
      size_t aStride, size_t cStride)
{
    __shared__ __align__(16) unsigned As[2][128 * LDA];
    __shared__ __align__(16) unsigned Bs[2][16 * LDB];

    int e = EXPERT ? blockIdx.z : 0;
    int Mloc = EXPERT ? cnt[e] : M;
    int mBase = blockIdx.y * 128;
    if (mBase >= Mloc) return;
    int nBase = blockIdx.x * 64;

    const float* W = W0; const float* bias = B0; float* C = C0;
    if (QKV) {
        int z = blockIdx.z;
        if (z == 1)      { W = Wx1; bias = Bx1; C = Cx1; }
        else if (z == 2) { W = Wx2; bias = Bx2; C = Cx2; }
    }
    const float* Ap = A;
    if (EXPERT) {
        W = W0 + (size_t)e * K * N;
        bias = B0 + (size_t)e * N;
        C = C0 + (size_t)e * cStride;
        if (!GATHER) Ap = A + (size_t)e * aStride;
    }

    int tid = threadIdx.x;
    int lane = tid & 31, warp = tid >> 5;
    int wM = (warp & 1) * 64;
    int wN = (warp >> 1) * 16;
    int g = lane >> 2, t = lane & 3;

    int r0 = tid >> 2;
    int r1 = r0 + 64;
    int ac4 = (tid & 3) * 4;
    int m0 = mBase + r0; m0 = m0 < Mloc ? m0 : Mloc - 1;
    int m1 = mBase + r1; m1 = m1 < Mloc ? m1 : Mloc - 1;
    int ar0 = GATHER ? gather[e * MAXM + m0] : m0;
    int ar1 = GATHER ? gather[e * MAXM + m1] : m1;
    const float* pA0 = Ap + (size_t)ar0 * K + ac4;
    const float* pA1 = Ap + (size_t)ar1 * K + ac4;

    int br  = tid >> 4;
    int bc4 = (tid & 15) * 4;
    const float* pB = W + (size_t)br * N + nBase + bc4;

    float acc[4][2][4];
    #pragma unroll
    for (int i = 0; i < 4; i++)
        #pragma unroll
        for (int j = 0; j < 2; j++)
            #pragma unroll
            for (int q = 0; q < 4; q++) acc[i][j][q] = 0.0f;

    float4 sa0 = *(const float4*)pA0;
    float4 sa1 = *(const float4*)pA1;
    float4 sb  = *(const float4*)pB;

    int buf = 0;
    for (int k0 = 0; k0 < K; k0 += 16) {
        unsigned* As_ = As[buf];
        unsigned* Bs_ = Bs[buf];
        // A already tf32-rounded: bit-store as two STS.128
        *(uint4*)&As_[r0 * LDA + ac4] = *reinterpret_cast<uint4*>(&sa0);
        *(uint4*)&As_[r1 * LDA + ac4] = *reinterpret_cast<uint4*>(&sa1);
        // B: convert then one packed STS.128
        uint4 ub;
        ub.x = f2tf(sb.x); ub.y = f2tf(sb.y); ub.z = f2tf(sb.z); ub.w = f2tf(sb.w);
        *(uint4*)&Bs_[br * LDB + bc4] = ub;
        __syncthreads();

        if (k0 + 16 < K) {
            sa0 = *(const float4*)(pA0 + k0 + 16);
            sa1 = *(const float4*)(pA1 + k0 + 16);
            sb  = *(const float4*)(pB + (size_t)(k0 + 16) * N);
        }

        #pragma unroll
        for (int ks = 0; ks < 2; ks++) {
            unsigned af[4][4], bf[2][2];
            #pragma unroll
            for (int mt = 0; mt < 4; mt++) {
                int base = (wM + mt * 16 + g) * LDA + ks * 8 + t;
                af[mt][0] = As_[base];
                af[mt][1] = As_[base + 8 * LDA];
                af[mt][2] = As_[base + 4];
                af[mt][3] = As_[base + 8 * LDA + 4];
            }
            #pragma unroll
            for (int nt = 0; nt < 2; nt++) {
                int base = (ks * 8 + t) * LDB + wN + nt * 8 + g;
                bf[nt][0] = Bs_[base];
                bf[nt][1] = Bs_[base + 4 * LDB];
            }
            #pragma unroll
            for (int mt = 0; mt < 4; mt++)
                #pragma unroll
                for (int nt = 0; nt < 2; nt++)
                    asm volatile(
                        "mma.sync.aligned.m16n8k8.row.col.f32.tf32.tf32.f32 "
                        "{%0,%1,%2,%3}, {%4,%5,%6,%7}, {%8,%9}, {%0,%1,%2,%3};"
                        : "+f"(acc[mt][nt][0]), "+f"(acc[mt][nt][1]),
                          "+f"(acc[mt][nt][2]), "+f"(acc[mt][nt][3])
                        : "r"(af[mt][0]), "r"(af[mt][1]), "r"(af[mt][2]), "r"(af[mt][3]),
                          "r"(bf[nt][0]), "r"(bf[nt][1]));
        }
        buf ^= 1;
    }

    #pragma unroll
    for (int mt = 0; mt < 4; mt++) {
        #pragma unroll
        for (int half = 0; half < 2; half++) {
            int r = mBase + wM + mt * 16 + g + half * 8;
            if (r < Mloc) {
                #pragma unroll
                for (int nt = 0; nt < 2; nt++) {
                    int col = nBase + wN + nt * 8 + 2 * t;
                    float* cp = C + (size_t)r * N + col;
                    float v0 = acc[mt][nt][half * 2 + 0] + bias[col];
                    float v1 = acc[mt][nt][half * 2 + 1] + bias[col + 1];
                    if (RELU) {
                        v0 = roundtf(fmaxf(v0, 0.0f));
                        v1 = roundtf(fmaxf(v1, 0.0f));
                    }
                    if (ACCUM) { cp[0] += v0; cp[1] += v1; }
                    else       { cp[0] = v0;  cp[1] = v1; }
                }
            }
        }
    }
}

// ---------------- flash-style single-pass attention ----------------
// Block = (b, h, 32-query tile); 256 threads; thread t = qq*8 + sub owns query
// row qq in BOTH the score role (8 keys j = sub+8m) and the PV role (d-slices
// sub, sub+8). Online softmax: 8-lane-group shuffle reductions keep m/l/alpha
// in-register. Smem 34.5 KB -> 6 blocks/SM -> all 512 blocks in one wave.
#define QT 32
#define KT 64
#define KVP 68                 // K/V & Q smem row pitch (floats)
#define PP 72                  // P smem row pitch (floats)

__global__ void __launch_bounds__(256)
attn3_kernel(const float* __restrict__ q, const float* __restrict__ k,
             const float* __restrict__ v, const int* __restrict__ abt,
             const float* __restrict__ bias_emb, float* __restrict__ o)
{
    __shared__ float Qs[QT * KVP];
    __shared__ float KVs[KT * KVP];
    __shared__ float Ps[QT * PP];

    int bid = blockIdx.x;
    int qt = bid & 7, h = (bid >> 3) & 15, b = bid >> 7;
    int q0 = qt * QT;
    int t = threadIdx.x;
    int qq = t >> 3, sub = t & 7;

    // load Q tile (scaled by 1/8): row = t>>3, 8 floats at (t&7)*8
    {
        int r = t >> 3, c = (t & 7) * 8;
        const float* qg = q + (size_t)(b * SEQ + q0 + r) * DMODEL + h * HDIM + c;
        float4 a0 = *(const float4*)qg;
        float4 a1 = *(const float4*)(qg + 4);
        float* dst = Qs + r * KVP + c;
        dst[0] = a0.x * 0.125f; dst[1] = a0.y * 0.125f; dst[2] = a0.z * 0.125f; dst[3] = a0.w * 0.125f;
        dst[4] = a1.x * 0.125f; dst[5] = a1.y * 0.125f; dst[6] = a1.z * 0.125f; dst[7] = a1.w * 0.125f;
    }
    __syncthreads();

    float m = -3.4e38f, l = 0.0f;
    float4 o0 = make_float4(0, 0, 0, 0);
    float4 o1 = make_float4(0, 0, 0, 0);

    for (int kt = 0; kt < 4; kt++) {
        int k0 = kt * KT;
        {   // coalesced K tile load: row = t>>2, 16 floats at (t&3)*16
            int r = t >> 2, c = (t & 3) * 16;
            const float* kg = k + (size_t)(b * SEQ + k0 + r) * DMODEL + h * HDIM + c;
            float4 x0 = *(const float4*)kg;
            float4 x1 = *(const float4*)(kg + 4);
            float4 x2 = *(const float4*)(kg + 8);
            float4 x3 = *(const float4*)(kg + 12);
            float* dst = KVs + r * KVP + c;
            *(float4*)(dst)      = x0;
            *(float4*)(dst + 4)  = x1;
            *(float4*)(dst + 8)  = x2;
            *(float4*)(dst + 12) = x3;
        }
        __syncthreads();

        // scores for keys j = sub + 8*jj
        float acc[8] = {0, 0, 0, 0, 0, 0, 0, 0};
        #pragma unroll
        for (int d4 = 0; d4 < 16; d4++) {
            float4 qv = *(const float4*)(Qs + qq * KVP + d4 * 4);
            #pragma unroll
            for (int j = 0; j < 8; j++) {
                float4 kv = *(const float4*)(KVs + (sub + 8 * j) * KVP + d4 * 4);
                acc[j] += qv.x * kv.x + qv.y * kv.y + qv.z * kv.z + qv.w * kv.w;
            }
        }
        const int* arow = abt + (size_t)(b * SEQ + q0 + qq) * SEQ + k0;
        float tm = -3.4e38f;
        #pragma unroll
        for (int j = 0; j < 8; j++) {
            acc[j] += bias_emb[arow[sub + 8 * j] * NH + h];
            tm = fmaxf(tm, acc[j]);
        }
        // row-tile max over the 8-lane group
        tm = fmaxf(tm, __shfl_xor_sync(0xffffffffu, tm, 4));
        tm = fmaxf(tm, __shfl_xor_sync(0xffffffffu, tm, 2));
        tm = fmaxf(tm, __shfl_xor_sync(0xffffffffu, tm, 1));
        float mnew = fmaxf(m, tm);
        float alpha = expf(m - mnew);
        float ts = 0.0f;
        #pragma unroll
        for (int j = 0; j < 8; j++) {
            float p = expf(acc[j] - mnew);
            Ps[qq * PP + sub + 8 * j] = p;
            ts += p;
        }
        ts += __shfl_xor_sync(0xffffffffu, ts, 4);
        ts += __shfl_xor_sync(0xffffffffu, ts, 2);
        ts += __shfl_xor_sync(0xffffffffu, ts, 1);
        l = l * alpha + ts;
        m = mnew;
        __syncthreads();   // Ps written; KVs reads done

        {   // coalesced V tile load (overwrites KVs)
            int r = t >> 2, c = (t & 3) * 16;
            const float* vg = v + (size_t)(b * SEQ + k0 + r) * DMODEL + h * HDIM + c;
            float4 x0 = *(const float4*)vg;
            float4 x1 = *(const float4*)(vg + 4);
            float4 x2 = *(const float4*)(vg + 8);
            float4 x3 = *(const float4*)(vg + 12);
            float* dst = KVs + r * KVP + c;
            *(float4*)(dst)      = x0;
            *(float4*)(dst + 4)  = x1;
            *(float4*)(dst + 8)  = x2;
            *(float4*)(dst + 12) = x3;
        }
        __syncthreads();

        // PV accumulate with rescale
        o0.x *= alpha; o0.y *= alpha; o0.z *= alpha; o0.w *= alpha;
        o1.x *= alpha; o1.y *= alpha; o1.z *= alpha; o1.w *= alpha;
        const float* prow = Ps + qq * PP;
        #pragma unroll
        for (int j4 = 0; j4 < 16; j4++) {
            float4 p4 = *(const float4*)(prow + j4 * 4);
            float pr[4] = {p4.x, p4.y, p4.z, p4.w};
            #pragma unroll
            for (int u = 0; u < 4; u++) {
                int j = j4 * 4 + u;
                float4 va = *(const float4*)(KVs + j * KVP + sub * 4);
                float4 vb = *(const float4*)(KVs + j * KVP + (sub + 8) * 4);
                float p = pr[u];
                o0.x += p * va.x; o0.y += p * va.y; o0.z += p * va.z; o0.w += p * va.w;
                o1.x += p * vb.x; o1.y += p * vb.y; o1.z += p * vb.z; o1.w += p * vb.w;
            }
        }
        __syncthreads();   // KVs reads done before next K load
    }

    float inv = 1.0f / l;
    o0.x = roundtf(o0.x * inv); o0.y = roundtf(o0.y * inv);
    o0.z = roundtf(o0.z * inv); o0.w = roundtf(o0.w * inv);
    o1.x = roundtf(o1.x * inv); o1.y = roundtf(o1.y * inv);
    o1.z = roundtf(o1.z * inv); o1.w = roundtf(o1.w * inv);
    float* og = o + (size_t)(b * SEQ + q0 + qq) * DMODEL + h * HDIM;
    *(float4*)(og + sub * 4) = o0;
    *(float4*)(og + 32 + sub * 4) = o1;
}

// ---------------- MoE routing ----------------
__global__ void route_kernel(const float* __restrict__ z, const float* __restrict__ gw,
                             const float* __restrict__ gb)
{
    __shared__ float lg[NE];
    int tok = blockIdx.x;
    int lane = threadIdx.x & 31, e = threadIdx.x >> 5;
    const float* zr = z + (size_t)tok * DMODEL;
    float s = 0.0f;
    for (int kk = lane; kk < DMODEL; kk += 32) s += zr[kk] * gw[kk * NE + e];
    #pragma unroll
    for (int off = 16; off > 0; off >>= 1) s += __shfl_down_sync(0xffffffffu, s, off);
    if (lane == 0) lg[e] = s + gb[e];
    __syncthreads();
    if (threadIdx.x == 0) {
        int i0 = 0; float v0 = lg[0];
        #pragma unroll
        for (int i = 1; i < NE; i++) if (lg[i] > v0) { v0 = lg[i]; i0 = i; }
        int i1 = -1; float v1 = -3.4e38f;
        #pragma unroll
        for (int i = 0; i < NE; i++) if (i != i0 && lg[i] > v1) { v1 = lg[i]; i1 = i; }
        float e1 = expf(v1 - v0);
        float invs = 1.0f / (1.0f + e1);
        float w0 = invs, w1 = e1 * invs;
        int p0 = atomicAdd(&g_cnt[i0], 1);
        g_ptok[i0 * MAXM + p0] = tok;
        g_pos[2 * tok] = i0 * MAXM + p0;
        g_wgt[2 * tok] = w0;
        int p1 = atomicAdd(&g_cnt[i1], 1);
        g_ptok[i1 * MAXM + p1] = tok;
        g_pos[2 * tok + 1] = i1 * MAXM + p1;
        g_wgt[2 * tok + 1] = w1;
    }
}

__global__ void combine_kernel()
{
    int tok = blockIdx.x, t = threadIdx.x;
    int p0 = g_pos[2 * tok], p1 = g_pos[2 * tok + 1];
    float w0 = g_wgt[2 * tok], w1 = g_wgt[2 * tok + 1];
    float4 a = ((const float4*)(g_y2 + (size_t)p0 * DMODEL))[t];
    float4 b = ((const float4*)(g_y2 + (size_t)p1 * DMODEL))[t];
    float4* f = (float4*)(g_feat + (size_t)tok * DMODEL);
    float4 fv = f[t];
    fv.x += w0 * a.x + w1 * b.x;
    fv.y += w0 * a.y + w1 * b.y;
    fv.z += w0 * a.z + w1 * b.z;
    fv.w += w0 * a.w + w1 * b.w;
    f[t] = fv;
}

// ---------------- host orchestration ----------------
extern "C" void kernel_launch(void* const* d_in, const int* in_sizes, int n_in,
                              void* d_out, int out_size)
{
    (void)in_sizes; (void)n_in; (void)out_size;
    const int*   et       = (const int*)d_in[0];
    const int*   xi       = (const int*)d_in[1];
    const int*   abt      = (const int*)d_in[2];
    const float* ent      = (const float*)d_in[3];
    const float* maskemb  = (const float*)d_in[4];
    const float* rel      = (const float*)d_in[5];
    const float* type     = (const float*)d_in[6];
    const float* bias_emb = (const float*)d_in[7];
    const float* ln1g     = (const float*)d_in[8];
    const float* ln1b     = (const float*)d_in[9];
    const float* wq       = (const float*)d_in[10];
    const float* bq       = (const float*)d_in[11];
    const float* wk       = (const float*)d_in[12];
    const float* bk       = (const float*)d_in[13];
    const float* wv       = (const float*)d_in[14];
    const float* bv       = (const float*)d_in[15];
    const float* wo       = (const float*)d_in[16];
    const float* bo       = (const float*)d_in[17];
    const float* ln2g     = (const float*)d_in[18];
    const float* ln2b     = (const float*)d_in[19];
    const float* gw       = (const float*)d_in[20];
    const float* gb       = (const float*)d_in[21];
    const float* w1       = (const float*)d_in[22];
    const float* b1       = (const float*)d_in[23];
    const float* w2       = (const float*)d_in[24];
    const float* b2       = (const float*)d_in[25];
    const float* flng     = (const float*)d_in[26];
    const float* flnb     = (const float*)d_in[27];
    float* out = (float*)d_out;

    float *feat, *xn, *xnr, *qb2, *kb2, *vb2, *ob, *hb, *yb;
    int *cntp, *ptokp;
    cudaGetSymbolAddress((void**)&feat,  g_feat);
    cudaGetSymbolAddress((void**)&xn,    g_xn);
    cudaGetSymbolAddress((void**)&xnr,   g_xnr);
    cudaGetSymbolAddress((void**)&qb2,   g_q);
    cudaGetSymbolAddress((void**)&kb2,   g_k);
    cudaGetSymbolAddress((void**)&vb2,   g_v);
    cudaGetSymbolAddress((void**)&ob,    g_o);
    cudaGetSymbolAddress((void**)&hb,    g_h);
    cudaGetSymbolAddress((void**)&yb,    g_y2);
    cudaGetSymbolAddress((void**)&cntp,  g_cnt);
    cudaGetSymbolAddress((void**)&ptokp, g_ptok);

    embed_kernel<<<NTOK, 256>>>(et, xi, ent, maskemb, rel, type);

    for (int l = 0; l < 2; l++) {
        const size_t dd = (size_t)DMODEL * DMODEL;
        // 1) LN1 -> xn + xnr (rounded, GEMM A)
        ln_kernel<<<NTOK, 256>>>(feat, ln1g + l * DMODEL, ln1b + l * DMODEL, xn, xnr, 0);
        // 2) fused q,k,v projections
        tgemm<0,0,0,0,1><<<dim3(16, 8, 3), 256>>>(
            xnr, wq + l * dd, wk + l * dd, wv + l * dd,
            bq + l * DMODEL, bk + l * DMODEL, bv + l * DMODEL,
            qb2, kb2, vb2,
            NTOK, DMODEL, DMODEL, (const int*)0, (const int*)0, 0, 0);
        // 3) attention (flash-style single pass); output pre-rounded
        attn3_kernel<<<NB * NH * (SEQ / QT), 256>>>(
            qb2, kb2, vb2, abt, bias_emb, ob);
        // 4) out proj + residual accumulate
        tgemm<0,1,0,0,0><<<dim3(16, 8), 256>>>(
            ob, wo + l * dd, (const float*)0, (const float*)0,
            bo + l * DMODEL, (const float*)0, (const float*)0,
            feat, (float*)0, (float*)0,
            NTOK, DMODEL, DMODEL, (const int*)0, (const int*)0, 0, 0);
        // 5) LN2 -> xn (exact, routing) + xnr (rounded); also clears g_cnt
        ln_kernel<<<NTOK, 256>>>(feat, ln2g + l * DMODEL, ln2b + l * DMODEL, xn, xnr, 1);
        // 6) routing on exact xn
        route_kernel<<<NTOK, 256>>>(xn, gw + (size_t)l * DMODEL * NE, gb + l * NE);
        // 7) expert up-proj + relu (gathered rows of xnr); output pre-rounded
        tgemm<1,0,1,1,0><<<dim3(32, 8, 8), 256>>>(
            xnr, w1 + (size_t)l * NE * DMODEL * DHID, (const float*)0, (const float*)0,
            b1 + (size_t)l * NE * DHID, (const float*)0, (const float*)0,
            hb, (float*)0, (float*)0,
            MAXM, DHID, DMODEL, ptokp, cntp, 0, (size_t)MAXM * DHID);
        // 8) expert down-proj
        tgemm<0,0,1,0,0><<<dim3(16, 8, 8), 256>>>(
            hb, w2 + (size_t)l * NE * DHID * DMODEL, (const float*)0, (const float*)0,
            b2 + (size_t)l * NE * DMODEL, (const float*)0, (const float*)0,
            yb, (float*)0, (float*)0,
            MAXM, DMODEL, DHID, (const int*)0, cntp, (size_t)MAXM * DHID, (size_t)MAXM * DMODEL);
        // 9) weighted combine into feat
        combine_kernel<<<NTOK, 256>>>();
    }

    // final layernorm -> out (exact); rounded copy goes to scratch
    ln_kernel<<<NTOK, 256>>>(feat, flng, flnb, out, xnr, 0);
}

// round 13
// speedup vs baseline: 1.1138x; 1.0508x over previous
#include <cuda_runtime.h>
#include <math.h>

// Problem constants
#define NTOK 1024      // B*S
#define DMODEL 1024
#define NH 16
#define HDIM 64
#define SEQ 256
#define NB 4
#define NE 8
#define DHID 2048
#define MAXM 1024      // max rows per expert

// ---------------- scratch (device globals; no allocation allowed) ----------------
__device__ float g_feat[NTOK * DMODEL];
__device__ float g_xn[NTOK * DMODEL];     // exact LN output (route reads this)
__device__ float g_xnr[NTOK * DMODEL];    // tf32-rounded LN output (GEMM A)
__device__ float g_q[NTOK * DMODEL];
__device__ float g_k[NTOK * DMODEL];
__device__ float g_v[NTOK * DMODEL];
__device__ float g_o[NTOK * DMODEL];
__device__ float g_h[NE * MAXM * DHID];    // expert hidden (tf32-rounded)
__device__ float g_y2[NE * MAXM * DMODEL]; // expert output
__device__ int   g_cnt[NE];
__device__ int   g_ptok[NE * MAXM];
__device__ int   g_pos[NTOK * 2];
__device__ float g_wgt[NTOK * 2];

__device__ __forceinline__ unsigned f2tf(float f) {
    unsigned u; asm("cvt.rna.tf32.f32 %0, %1;" : "=r"(u) : "f"(f)); return u;
}
__device__ __forceinline__ float roundtf(float f) {
    return __uint_as_float(f2tf(f));
}

// ---------------- embedding ----------------
__global__ void embed_kernel(const int* __restrict__ et, const int* __restrict__ xi,
                             const float* __restrict__ ent, const float* __restrict__ maskemb,
                             const float* __restrict__ rel, const float* __restrict__ type)
{
    int tok = blockIdx.x, t = threadIdx.x;   // 256 threads, 1 float4 each
    int ty = et[tok];
    int xv = xi[tok];
    const float* src;
    if (ty == 0)      src = ent + (size_t)(((unsigned)xv) % 40000u) * DMODEL;
    else if (ty == 1) src = maskemb;
    else              src = rel + (size_t)(((unsigned)xv) % 1000u) * DMODEL;
    float4 s4 = ((const float4*)src)[t];
    float4 t4 = ((const float4*)(type + (size_t)ty * DMODEL))[t];
    float4 r = make_float4(s4.x + t4.x, s4.y + t4.y, s4.z + t4.z, s4.w + t4.w);
    ((float4*)(g_feat + (size_t)tok * DMODEL))[t] = r;
}

// ---------------- layernorm: writes exact y and tf32-rounded yr ----------------
// clearcnt != 0: block 0 also resets the MoE counters (folds the reset launch).
__global__ void ln_kernel(const float* __restrict__ x, const float* __restrict__ g,
                          const float* __restrict__ b, float* __restrict__ y,
                          float* __restrict__ yr, int clearcnt)
{
    __shared__ float red[256];
    int row = blockIdx.x, t = threadIdx.x;
    if (clearcnt && row == 0 && t < NE) g_cnt[t] = 0;
    float4 xv = ((const float4*)(x + (size_t)row * DMODEL))[t];
    red[t] = xv.x + xv.y + xv.z + xv.w;
    __syncthreads();
    #pragma unroll
    for (int off = 128; off > 0; off >>= 1) { if (t < off) red[t] += red[t + off]; __syncthreads(); }
    float m = red[0] * (1.0f / DMODEL);
    __syncthreads();
    float dx = xv.x - m, dy = xv.y - m, dz = xv.z - m, dw = xv.w - m;
    red[t] = dx * dx + dy * dy + dz * dz + dw * dw;
    __syncthreads();
    #pragma unroll
    for (int off = 128; off > 0; off >>= 1) { if (t < off) red[t] += red[t + off]; __syncthreads(); }
    float rs = rsqrtf(red[0] * (1.0f / DMODEL) + 1e-5f);
    float4 gv = ((const float4*)g)[t];
    float4 bv = ((const float4*)b)[t];
    float4 o = make_float4(dx * rs * gv.x + bv.x, dy * rs * gv.y + bv.y,
                           dz * rs * gv.z + bv.z, dw * rs * gv.w + bv.w);
    ((float4*)(y + (size_t)row * DMODEL))[t] = o;
    float4 orr = make_float4(roundtf(o.x), roundtf(o.y), roundtf(o.z), roundtf(o.w));
    ((float4*)(yr + (size_t)row * DMODEL))[t] = orr;
}

// ---------------- TF32 tensor-core GEMM (static double-buffer) ----------------
// A is PRE-ROUNDED to tf32 (RNA) by its producer.
#define LDA 20
#define LDB 72

template<int RELU, int ACCUM, int EXPERT, int GATHER, int QKV>
__global__ void __launch_bounds__(256)
tgemm(const float* __restrict__ A,
      const float* __restrict__ W0, const float* __restrict__ Wx1, const float* __restrict__ Wx2,
      const float* __restrict__ B0, const float* __restrict__ Bx1, const float* __restrict__ Bx2,
      float* __restrict__ C0, float* __restrict__ Cx1, float* __restrict__ Cx2,
      int M, int N, int K,
      const int* __restrict__ gather, const int* __restrict__ cnt,
      size_t aStride, size_t cStride)
{
    __shared__ __align__(16) unsigned As[2][128 * LDA];
    __shared__ __align__(16) unsigned Bs[2][16 * LDB];

    int e = EXPERT ? blockIdx.z : 0;
    int Mloc = EXPERT ? cnt[e] : M;
    int mBase = blockIdx.y * 128;
    if (mBase >= Mloc) return;
    int nBase = blockIdx.x * 64;

    const float* W = W0; const float* bias = B0; float* C = C0;
    if (QKV) {
        int z = blockIdx.z;
        if (z == 1)      { W = Wx1; bias = Bx1; C = Cx1; }
        else if (z == 2) { W = Wx2; bias = Bx2; C = Cx2; }
    }
    const float* Ap = A;
    if (EXPERT) {
        W = W0 + (size_t)e * K * N;
        bias = B0 + (size_t)e * N;
        C = C0 + (size_t)e * cStride;
        if (!GATHER) Ap = A + (size_t)e * aStride;
    }

    int tid = threadIdx.x;
    int lane = tid & 31, warp = tid >> 5;
    int wM = (warp & 1) * 64;
    int wN = (warp >> 1) * 16;
    int g = lane >> 2, t = lane & 3;

    int r0 = tid >> 2;
    int r1 = r0 + 64;
    int ac4 = (tid & 3) * 4;
    int m0 = mBase + r0; m0 = m0 < Mloc ? m0 : Mloc - 1;
    int m1 = mBase + r1; m1 = m1 < Mloc ? m1 : Mloc - 1;
    int ar0 = GATHER ? gather[e * MAXM + m0] : m0;
    int ar1 = GATHER ? gather[e * MAXM + m1] : m1;
    const float* pA0 = Ap + (size_t)ar0 * K + ac4;
    const float* pA1 = Ap + (size_t)ar1 * K + ac4;

    int br  = tid >> 4;
    int bc4 = (tid & 15) * 4;
    const float* pB = W + (size_t)br * N + nBase + bc4;

    float acc[4][2][4];
    #pragma unroll
    for (int i = 0; i < 4; i++)
        #pragma unroll
        for (int j = 0; j < 2; j++)
            #pragma unroll
            for (int q = 0; q < 4; q++) acc[i][j][q] = 0.0f;

    float4 sa0 = *(const float4*)pA0;
    float4 sa1 = *(const float4*)pA1;
    float4 sb  = *(const float4*)pB;

    int buf = 0;
    for (int k0 = 0; k0 < K; k0 += 16) {
        unsigned* As_ = As[buf];
        unsigned* Bs_ = Bs[buf];
        *(uint4*)&As_[r0 * LDA + ac4] = *reinterpret_cast<uint4*>(&sa0);
        *(uint4*)&As_[r1 * LDA + ac4] = *reinterpret_cast<uint4*>(&sa1);
        uint4 ub;
        ub.x = f2tf(sb.x); ub.y = f2tf(sb.y); ub.z = f2tf(sb.z); ub.w = f2tf(sb.w);
        *(uint4*)&Bs_[br * LDB + bc4] = ub;
        __syncthreads();

        if (k0 + 16 < K) {
            sa0 = *(const float4*)(pA0 + k0 + 16);
            sa1 = *(const float4*)(pA1 + k0 + 16);
            sb  = *(const float4*)(pB + (size_t)(k0 + 16) * N);
        }

        #pragma unroll
        for (int ks = 0; ks < 2; ks++) {
            unsigned af[4][4], bf[2][2];
            #pragma unroll
            for (int mt = 0; mt < 4; mt++) {
                int base = (wM + mt * 16 + g) * LDA + ks * 8 + t;
                af[mt][0] = As_[base];
                af[mt][1] = As_[base + 8 * LDA];
                af[mt][2] = As_[base + 4];
                af[mt][3] = As_[base + 8 * LDA + 4];
            }
            #pragma unroll
            for (int nt = 0; nt < 2; nt++) {
                int base = (ks * 8 + t) * LDB + wN + nt * 8 + g;
                bf[nt][0] = Bs_[base];
                bf[nt][1] = Bs_[base + 4 * LDB];
            }
            #pragma unroll
            for (int mt = 0; mt < 4; mt++)
                #pragma unroll
                for (int nt = 0; nt < 2; nt++)
                    asm volatile(
                        "mma.sync.aligned.m16n8k8.row.col.f32.tf32.tf32.f32 "
                        "{%0,%1,%2,%3}, {%4,%5,%6,%7}, {%8,%9}, {%0,%1,%2,%3};"
                        : "+f"(acc[mt][nt][0]), "+f"(acc[mt][nt][1]),
                          "+f"(acc[mt][nt][2]), "+f"(acc[mt][nt][3])
                        : "r"(af[mt][0]), "r"(af[mt][1]), "r"(af[mt][2]), "r"(af[mt][3]),
                          "r"(bf[nt][0]), "r"(bf[nt][1]));
        }
        buf ^= 1;
    }

    #pragma unroll
    for (int mt = 0; mt < 4; mt++) {
        #pragma unroll
        for (int half = 0; half < 2; half++) {
            int r = mBase + wM + mt * 16 + g + half * 8;
            if (r < Mloc) {
                #pragma unroll
                for (int nt = 0; nt < 2; nt++) {
                    int col = nBase + wN + nt * 8 + 2 * t;
                    float* cp = C + (size_t)r * N + col;
                    float v0 = acc[mt][nt][half * 2 + 0] + bias[col];
                    float v1 = acc[mt][nt][half * 2 + 1] + bias[col + 1];
                    if (RELU) {
                        v0 = roundtf(fmaxf(v0, 0.0f));
                        v1 = roundtf(fmaxf(v1, 0.0f));
                    }
                    if (ACCUM) { cp[0] += v0; cp[1] += v1; }
                    else       { cp[0] = v0;  cp[1] = v1; }
                }
            }
        }
    }
}

// ---------------- flash attention, 2-query register blocking ----------------
// Block = (b, h, 32-query tile); 256 threads. Thread t:
//   qpair = t>>4 (owns query rows 2*qpair, 2*qpair+1)
//   scores: kk = t&15 -> keys j = kk + 16*jj (jj<4), for BOTH queries
//   PV:     sub = t&7 (d-slices sub*4, 32+sub*4), vhalf = (t>>3)&1 (keys half)
// Partial PV sums combined with shfl_xor(…,8); softmax reductions over the
// 16-lane group (xor 8,4,2,1). Online softmax identical to reference.
#define QT 32
#define KT 64
#define KVP 68                 // K/V & Q smem row pitch (floats)
#define PP 72                  // P smem row pitch (floats)

__global__ void __launch_bounds__(256)
attn4_kernel(const float* __restrict__ q, const float* __restrict__ k,
             const float* __restrict__ v, const int* __restrict__ abt,
             const float* __restrict__ bias_emb, float* __restrict__ o)
{
    __shared__ float Qs[QT * KVP];
    __shared__ float KVs[KT * KVP];
    __shared__ float Ps[QT * PP];

    int bid = blockIdx.x;
    int qt = bid & 7, h = (bid >> 3) & 15, b = bid >> 7;
    int q0 = qt * QT;
    int t = threadIdx.x;
    int qpair = t >> 4;
    int q2 = qpair * 2;
    int kk = t & 15;
    int sub = t & 7, vhalf = (t >> 3) & 1;

    // load Q tile (scaled by 1/8): row = t>>3, 8 floats at (t&7)*8
    {
        int r = t >> 3, c = (t & 7) * 8;
        const float* qg = q + (size_t)(b * SEQ + q0 + r) * DMODEL + h * HDIM + c;
        float4 a0 = *(const float4*)qg;
        float4 a1 = *(const float4*)(qg + 4);
        float* dst = Qs + r * KVP + c;
        dst[0] = a0.x * 0.125f; dst[1] = a0.y * 0.125f; dst[2] = a0.z * 0.125f; dst[3] = a0.w * 0.125f;
        dst[4] = a1.x * 0.125f; dst[5] = a1.y * 0.125f; dst[6] = a1.z * 0.125f; dst[7] = a1.w * 0.125f;
    }
    __syncthreads();

    float m0r = -3.4e38f, m1r = -3.4e38f, l0r = 0.0f, l1r = 0.0f;
    float4 oA0 = make_float4(0, 0, 0, 0), oA1 = make_float4(0, 0, 0, 0);
    float4 oB0 = make_float4(0, 0, 0, 0), oB1 = make_float4(0, 0, 0, 0);

    for (int kt = 0; kt < 4; kt++) {
        int k0 = kt * KT;
        {   // coalesced K tile load: row = t>>2, 16 floats at (t&3)*16
            int r = t >> 2, c = (t & 3) * 16;
            const float* kg = k + (size_t)(b * SEQ + k0 + r) * DMODEL + h * HDIM + c;
            float4 x0 = *(const float4*)kg;
            float4 x1 = *(const float4*)(kg + 4);
            float4 x2 = *(const float4*)(kg + 8);
            float4 x3 = *(const float4*)(kg + 12);
            float* dst = KVs + r * KVP + c;
            *(float4*)(dst)      = x0;
            *(float4*)(dst + 4)  = x1;
            *(float4*)(dst + 8)  = x2;
            *(float4*)(dst + 12) = x3;
        }
        __syncthreads();

        // scores: 2 queries x 4 keys (j = kk + 16*jj)
        float acc0[4] = {0, 0, 0, 0}, acc1[4] = {0, 0, 0, 0};
        const float* qrow0 = Qs + q2 * KVP;
        const float* qrow1 = qrow0 + KVP;
        #pragma unroll
        for (int d4 = 0; d4 < 16; d4++) {
            float4 qa = *(const float4*)(qrow0 + d4 * 4);
            float4 qb = *(const float4*)(qrow1 + d4 * 4);
            #pragma unroll
            for (int jj = 0; jj < 4; jj++) {
                float4 kv = *(const float4*)(KVs + (kk + 16 * jj) * KVP + d4 * 4);
                acc0[jj] += qa.x * kv.x + qa.y * kv.y + qa.z * kv.z + qa.w * kv.w;
                acc1[jj] += qb.x * kv.x + qb.y * kv.y + qb.z * kv.z + qb.w * kv.w;
            }
        }
        const int* arow0 = abt + (size_t)(b * SEQ + q0 + q2) * SEQ + k0;
        const int* arow1 = arow0 + SEQ;
        float tm0 = -3.4e38f, tm1 = -3.4e38f;
        #pragma unroll
        for (int jj = 0; jj < 4; jj++) {
            acc0[jj] += bias_emb[arow0[kk + 16 * jj] * NH + h];
            acc1[jj] += bias_emb[arow1[kk + 16 * jj] * NH + h];
            tm0 = fmaxf(tm0, acc0[jj]);
            tm1 = fmaxf(tm1, acc1[jj]);
        }
        // reduce tile-max over the 16-lane group
        #pragma unroll
        for (int off = 8; off > 0; off >>= 1) {
            tm0 = fmaxf(tm0, __shfl_xor_sync(0xffffffffu, tm0, off));
            tm1 = fmaxf(tm1, __shfl_xor_sync(0xffffffffu, tm1, off));
        }
        float mn0 = fmaxf(m0r, tm0), mn1 = fmaxf(m1r, tm1);
        float a0 = expf(m0r - mn0), a1 = expf(m1r - mn1);
        float ts0 = 0.0f, ts1 = 0.0f;
        #pragma unroll
        for (int jj = 0; jj < 4; jj++) {
            float p0 = expf(acc0[jj] - mn0);
            float p1 = expf(acc1[jj] - mn1);
            Ps[q2 * PP + kk + 16 * jj] = p0;
            Ps[(q2 + 1) * PP + kk + 16 * jj] = p1;
            ts0 += p0; ts1 += p1;
        }
        #pragma unroll
        for (int off = 8; off > 0; off >>= 1) {
            ts0 += __shfl_xor_sync(0xffffffffu, ts0, off);
            ts1 += __shfl_xor_sync(0xffffffffu, ts1, off);
        }
        l0r = l0r * a0 + ts0; m0r = mn0;
        l1r = l1r * a1 + ts1; m1r = mn1;
        __syncthreads();   // Ps written; KVs reads done

        {   // coalesced V tile load (overwrites KVs)
            int r = t >> 2, c = (t & 3) * 16;
            const float* vg = v + (size_t)(b * SEQ + k0 + r) * DMODEL + h * HDIM + c;
            float4 x0 = *(const float4*)vg;
            float4 x1 = *(const float4*)(vg + 4);
            float4 x2 = *(const float4*)(vg + 8);
            float4 x3 = *(const float4*)(vg + 12);
            float* dst = KVs + r * KVP + c;
            *(float4*)(dst)      = x0;
            *(float4*)(dst + 4)  = x1;
            *(float4*)(dst + 8)  = x2;
            *(float4*)(dst + 12) = x3;
        }
        __syncthreads();

        // PV accumulate: this thread covers keys [vhalf*32, vhalf*32+32)
        oA0.x *= a0; oA0.y *= a0; oA0.z *= a0; oA0.w *= a0;
        oA1.x *= a0; oA1.y *= a0; oA1.z *= a0; oA1.w *= a0;
        oB0.x *= a1; oB0.y *= a1; oB0.z *= a1; oB0.w *= a1;
        oB1.x *= a1; oB1.y *= a1; oB1.z *= a1; oB1.w *= a1;
        const float* p0 = Ps + q2 * PP + vhalf * 32;
        const float* p1 = p0 + PP;
        #pragma unroll
        for (int j4 = 0; j4 < 8; j4++) {
            float4 pa = *(const float4*)(p0 + j4 * 4);
            float4 pb = *(const float4*)(p1 + j4 * 4);
            float par[4] = {pa.x, pa.y, pa.z, pa.w};
            float pbr[4] = {pb.x, pb.y, pb.z, pb.w};
            #pragma unroll
            for (int u = 0; u < 4; u++) {
                int j = vhalf * 32 + j4 * 4 + u;
                float4 va = *(const float4*)(KVs + j * KVP + sub * 4);
                float4 vb = *(const float4*)(KVs + j * KVP + (sub + 8) * 4);
                float pA = par[u], pB = pbr[u];
                oA0.x += pA * va.x; oA0.y += pA * va.y; oA0.z += pA * va.z; oA0.w += pA * va.w;
                oA1.x += pA * vb.x; oA1.y += pA * vb.y; oA1.z += pA * vb.z; oA1.w += pA * vb.w;
                oB0.x += pB * va.x; oB0.y += pB * va.y; oB0.z += pB * va.z; oB0.w += pB * va.w;
                oB1.x += pB * vb.x; oB1.y += pB * vb.y; oB1.z += pB * vb.z; oB1.w += pB * vb.w;
            }
        }
        __syncthreads();   // KVs reads done before next K load
    }

    // combine the two key-halves (lanes differing in bit 3)
    #pragma unroll
    for (int c = 0; c < 4; c++) {
        ((float*)&oA0)[c] += __shfl_xor_sync(0xffffffffu, ((float*)&oA0)[c], 8);
        ((float*)&oA1)[c] += __shfl_xor_sync(0xffffffffu, ((float*)&oA1)[c], 8);
        ((float*)&oB0)[c] += __shfl_xor_sync(0xffffffffu, ((float*)&oB0)[c], 8);
        ((float*)&oB1)[c] += __shfl_xor_sync(0xffffffffu, ((float*)&oB1)[c], 8);
    }

    // thread writes query q2+vhalf
    float invq = (vhalf == 0) ? (1.0f / l0r) : (1.0f / l1r);
    float4 w0 = (vhalf == 0) ? oA0 : oB0;
    float4 w1 = (vhalf == 0) ? oA1 : oB1;
    w0.x = roundtf(w0.x * invq); w0.y = roundtf(w0.y * invq);
    w0.z = roundtf(w0.z * invq); w0.w = roundtf(w0.w * invq);
    w1.x = roundtf(w1.x * invq); w1.y = roundtf(w1.y * invq);
    w1.z = roundtf(w1.z * invq); w1.w = roundtf(w1.w * invq);
    float* og = o + (size_t)(b * SEQ + q0 + q2 + vhalf) * DMODEL + h * HDIM;
    *(float4*)(og + sub * 4) = w0;
    *(float4*)(og + 32 + sub * 4) = w1;
}

// ---------------- MoE routing ----------------
__global__ void route_kernel(const float* __restrict__ z, const float* __restrict__ gw,
                             const float* __restrict__ gb)
{
    __shared__ float lg[NE];
    int tok = blockIdx.x;
    int lane = threadIdx.x & 31, e = threadIdx.x >> 5;
    const float* zr = z + (size_t)tok * DMODEL;
    float s = 0.0f;
    for (int kk = lane; kk < DMODEL; kk += 32) s += zr[kk] * gw[kk * NE + e];
    #pragma unroll
    for (int off = 16; off > 0; off >>= 1) s += __shfl_down_sync(0xffffffffu, s, off);
    if (lane == 0) lg[e] = s + gb[e];
    __syncthreads();
    if (threadIdx.x == 0) {
        int i0 = 0; float v0 = lg[0];
        #pragma unroll
        for (int i = 1; i < NE; i++) if (lg[i] > v0) { v0 = lg[i]; i0 = i; }
        int i1 = -1; float v1 = -3.4e38f;
        #pragma unroll
        for (int i = 0; i < NE; i++) if (i != i0 && lg[i] > v1) { v1 = lg[i]; i1 = i; }
        float e1 = expf(v1 - v0);
        float invs = 1.0f / (1.0f + e1);
        float w0 = invs, w1 = e1 * invs;
        int p0 = atomicAdd(&g_cnt[i0], 1);
        g_ptok[i0 * MAXM + p0] = tok;
        g_pos[2 * tok] = i0 * MAXM + p0;
        g_wgt[2 * tok] = w0;
        int p1 = atomicAdd(&g_cnt[i1], 1);
        g_ptok[i1 * MAXM + p1] = tok;
        g_pos[2 * tok + 1] = i1 * MAXM + p1;
        g_wgt[2 * tok + 1] = w1;
    }
}

__global__ void combine_kernel()
{
    int tok = blockIdx.x, t = threadIdx.x;
    int p0 = g_pos[2 * tok], p1 = g_pos[2 * tok + 1];
    float w0 = g_wgt[2 * tok], w1 = g_wgt[2 * tok + 1];
    float4 a = ((const float4*)(g_y2 + (size_t)p0 * DMODEL))[t];
    float4 b = ((const float4*)(g_y2 + (size_t)p1 * DMODEL))[t];
    float4* f = (float4*)(g_feat + (size_t)tok * DMODEL);
    float4 fv = f[t];
    fv.x += w0 * a.x + w1 * b.x;
    fv.y += w0 * a.y + w1 * b.y;
    fv.z += w0 * a.z + w1 * b.z;
    fv.w += w0 * a.w + w1 * b.w;
    f[t] = fv;
}

// ---------------- host orchestration ----------------
extern "C" void kernel_launch(void* const* d_in, const int* in_sizes, int n_in,
                              void* d_out, int out_size)
{
    (void)in_sizes; (void)n_in; (void)out_size;
    const int*   et       = (const int*)d_in[0];
    const int*   xi       = (const int*)d_in[1];
    const int*   abt      = (const int*)d_in[2];
    const float* ent      = (const float*)d_in[3];
    const float* maskemb  = (const float*)d_in[4];
    const float* rel      = (const float*)d_in[5];
    const float* type     = (const float*)d_in[6];
    const float* bias_emb = (const float*)d_in[7];
    const float* ln1g     = (const float*)d_in[8];
    const float* ln1b     = (const float*)d_in[9];
    const float* wq       = (const float*)d_in[10];
    const float* bq       = (const float*)d_in[11];
    const float* wk       = (const float*)d_in[12];
    const float* bk       = (const float*)d_in[13];
    const float* wv       = (const float*)d_in[14];
    const float* bv       = (const float*)d_in[15];
    const float* wo       = (const float*)d_in[16];
    const float* bo       = (const float*)d_in[17];
    const float* ln2g     = (const float*)d_in[18];
    const float* ln2b     = (const float*)d_in[19];
    const float* gw       = (const float*)d_in[20];
    const float* gb       = (const float*)d_in[21];
    const float* w1       = (const float*)d_in[22];
    const float* b1       = (const float*)d_in[23];
    const float* w2       = (const float*)d_in[24];
    const float* b2       = (const float*)d_in[25];
    const float* flng     = (const float*)d_in[26];
    const float* flnb     = (const float*)d_in[27];
    float* out = (float*)d_out;

    float *feat, *xn, *xnr, *qb2, *kb2, *vb2, *ob, *hb, *yb;
    int *cntp, *ptokp;
    cudaGetSymbolAddress((void**)&feat,  g_feat);
    cudaGetSymbolAddress((void**)&xn,    g_xn);
    cudaGetSymbolAddress((void**)&xnr,   g_xnr);
    cudaGetSymbolAddress((void**)&qb2,   g_q);
    cudaGetSymbolAddress((void**)&kb2,   g_k);
    cudaGetSymbolAddress((void**)&vb2,   g_v);
    cudaGetSymbolAddress((void**)&ob,    g_o);
    cudaGetSymbolAddress((void**)&hb,    g_h);
    cudaGetSymbolAddress((void**)&yb,    g_y2);
    cudaGetSymbolAddress((void**)&cntp,  g_cnt);
    cudaGetSymbolAddress((void**)&ptokp, g_ptok);

    embed_kernel<<<NTOK, 256>>>(et, xi, ent, maskemb, rel, type);

    for (int l = 0; l < 2; l++) {
        const size_t dd = (size_t)DMODEL * DMODEL;
        // 1) LN1 -> xn + xnr (rounded, GEMM A)
        ln_kernel<<<NTOK, 256>>>(feat, ln1g + l * DMODEL, ln1b + l * DMODEL, xn, xnr, 0);
        // 2) fused q,k,v projections
        tgemm<0,0,0,0,1><<<dim3(16, 8, 3), 256>>>(
            xnr, wq + l * dd, wk + l * dd, wv + l * dd,
            bq + l * DMODEL, bk + l * DMODEL, bv + l * DMODEL,
            qb2, kb2, vb2,
            NTOK, DMODEL, DMODEL, (const int*)0, (const int*)0, 0, 0);
        // 3) attention (flash, 2-query register blocking); output pre-rounded
        attn4_kernel<<<NB * NH * (SEQ / QT), 256>>>(
            qb2, kb2, vb2, abt, bias_emb, ob);
        // 4) out proj + residual accumulate
        tgemm<0,1,0,0,0><<<dim3(16, 8), 256>>>(
            ob, wo + l * dd, (const float*)0, (const float*)0,
            bo + l * DMODEL, (const float*)0, (const float*)0,
            feat, (float*)0, (float*)0,
            NTOK, DMODEL, DMODEL, (const int*)0, (const int*)0, 0, 0);
        // 5) LN2 -> xn (exact, routing) + xnr (rounded); also clears g_cnt
        ln_kernel<<<NTOK, 256>>>(feat, ln2g + l * DMODEL, ln2b + l * DMODEL, xn, xnr, 1);
        // 6) routing on exact xn
        route_kernel<<<NTOK, 256>>>(xn, gw + (size_t)l * DMODEL * NE, gb + l * NE);
        // 7) expert up-proj + relu (gathered rows of xnr); output pre-rounded
        tgemm<1,0,1,1,0><<<dim3(32, 8, 8), 256>>>(
            xnr, w1 + (size_t)l * NE * DMODEL * DHID, (const float*)0, (const float*)0,
            b1 + (size_t)l * NE * DHID, (const float*)0, (const float*)0,
            hb, (float*)0, (float*)0,
            MAXM, DHID, DMODEL, ptokp, cntp, 0, (size_t)MAXM * DHID);
        // 8) expert down-proj
        tgemm<0,0,1,0,0><<<dim3(16, 8, 8), 256>>>(
            hb, w2 + (size_t)l * NE * DHID * DMODEL, (const float*)0, (const float*)0,
            b2 + (size_t)l * NE * DMODEL, (const float*)0, (const float*)0,
            yb, (float*)0, (float*)0,
            MAXM, DMODEL, DHID, (const int*)0, cntp, (size_t)MAXM * DHID, (size_t)MAXM * DMODEL);
        // 9) weighted combine into feat
        combine_kernel<<<NTOK, 256>>>();
    }

    // final layernorm -> out (exact); rounded copy goes to scratch
    ln_kernel<<<NTOK, 256>>>(feat, flng, flnb, out, xnr, 0);
}

// round 14
// speedup vs baseline: 1.1303x; 1.0148x over previous
#include <cuda_runtime.h>
#include <math.h>

// Problem constants
#define NTOK 1024      // B*S
#define DMODEL 1024
#define NH 16
#define HDIM 64
#define SEQ 256
#define NB 4
#define NE 8
#define DHID 2048
#define MAXM 1024      // max rows per expert

// ---------------- scratch (device globals; no allocation allowed) ----------------
__device__ float g_feat[NTOK * DMODEL];
__device__ float g_xnr[NTOK * DMODEL];    // tf32-rounded LN output (GEMM A)
__device__ float g_q[NTOK * DMODEL];
__device__ float g_k[NTOK * DMODEL];
__device__ float g_v[NTOK * DMODEL];
__device__ float g_o[NTOK * DMODEL];
__device__ float g_h[NE * MAXM * DHID];    // expert hidden (tf32-rounded)
__device__ float g_y2[NE * MAXM * DMODEL]; // expert output
__device__ int   g_cnt[NE];
__device__ int   g_ptok[NE * MAXM];
__device__ int   g_pos[NTOK * 2];
__device__ float g_wgt[NTOK * 2];

__device__ __forceinline__ unsigned f2tf(float f) {
    unsigned u; asm("cvt.rna.tf32.f32 %0, %1;" : "=r"(u) : "f"(f)); return u;
}
__device__ __forceinline__ float roundtf(float f) {
    return __uint_as_float(f2tf(f));
}

// ---------------- embedding ----------------
__global__ void embed_kernel(const int* __restrict__ et, const int* __restrict__ xi,
                             const float* __restrict__ ent, const float* __restrict__ maskemb,
                             const float* __restrict__ rel, const float* __restrict__ type)
{
    int tok = blockIdx.x, t = threadIdx.x;   // 256 threads, 1 float4 each
    int ty = et[tok];
    int xv = xi[tok];
    const float* src;
    if (ty == 0)      src = ent + (size_t)(((unsigned)xv) % 40000u) * DMODEL;
    else if (ty == 1) src = maskemb;
    else              src = rel + (size_t)(((unsigned)xv) % 1000u) * DMODEL;
    float4 s4 = ((const float4*)src)[t];
    float4 t4 = ((const float4*)(type + (size_t)ty * DMODEL))[t];
    float4 r = make_float4(s4.x + t4.x, s4.y + t4.y, s4.z + t4.z, s4.w + t4.w);
    ((float4*)(g_feat + (size_t)tok * DMODEL))[t] = r;
}

// ---------------- fused layernorm (+optional combine / routing / cnt-clear) --------
// COMBINE: apply MoE weighted expert outputs to the feat row first, write feat back.
// ROUTE:   after LN, compute gate logits from the exact row (smem) and do top-2.
// EXACT:   write exact LN output to y (final LN -> out); else write tf32-rounded.
// CLEARCNT: block 0 clears g_cnt (safe: runs layers before that layer's routing).
template<int COMBINE, int ROUTE, int EXACT, int CLEARCNT>
__global__ void __launch_bounds__(256)
lnf_kernel(const float* __restrict__ x, const float* __restrict__ g,
           const float* __restrict__ b, float* __restrict__ y,
           const float* __restrict__ gw, const float* __restrict__ gb)
{
    __shared__ float ws[8], ws2[8], lg[NE];
    __shared__ float rowbuf[DMODEL];

    int row = blockIdx.x, t = threadIdx.x;
    int lane = t & 31, warp = t >> 5;
    if (CLEARCNT && row == 0 && t < NE) g_cnt[t] = 0;

    float4 xv = ((const float4*)(x + (size_t)row * DMODEL))[t];
    if (COMBINE) {
        int p0 = g_pos[2 * row], p1 = g_pos[2 * row + 1];
        float w0 = g_wgt[2 * row], w1 = g_wgt[2 * row + 1];
        float4 a = ((const float4*)(g_y2 + (size_t)p0 * DMODEL))[t];
        float4 c = ((const float4*)(g_y2 + (size_t)p1 * DMODEL))[t];
        xv.x += w0 * a.x + w1 * c.x;
        xv.y += w0 * a.y + w1 * c.y;
        xv.z += w0 * a.z + w1 * c.z;
        xv.w += w0 * a.w + w1 * c.w;
        ((float4*)(g_feat + (size_t)row * DMODEL))[t] = xv;  // residual stream update
    }

    // mean (warp shuffles + 8-wide combine)
    float s = xv.x + xv.y + xv.z + xv.w;
    #pragma unroll
    for (int off = 16; off > 0; off >>= 1) s += __shfl_xor_sync(0xffffffffu, s, off);
    if (lane == 0) ws[warp] = s;
    __syncthreads();
    float m = (ws[0] + ws[1] + ws[2] + ws[3] + ws[4] + ws[5] + ws[6] + ws[7]) * (1.0f / DMODEL);

    float dx = xv.x - m, dy = xv.y - m, dz = xv.z - m, dw = xv.w - m;
    float s2 = dx * dx + dy * dy + dz * dz + dw * dw;
    #pragma unroll
    for (int off = 16; off > 0; off >>= 1) s2 += __shfl_xor_sync(0xffffffffu, s2, off);
    if (lane == 0) ws2[warp] = s2;
    __syncthreads();
    float v = (ws2[0] + ws2[1] + ws2[2] + ws2[3] + ws2[4] + ws2[5] + ws2[6] + ws2[7]) * (1.0f / DMODEL);
    float rs = rsqrtf(v + 1e-5f);

    float4 gv = ((const float4*)g)[t];
    float4 bv = ((const float4*)b)[t];
    float4 o = make_float4(dx * rs * gv.x + bv.x, dy * rs * gv.y + bv.y,
                           dz * rs * gv.z + bv.z, dw * rs * gv.w + bv.w);
    if (EXACT) {
        ((float4*)(y + (size_t)row * DMODEL))[t] = o;
    } else {
        float4 orr = make_float4(roundtf(o.x), roundtf(o.y), roundtf(o.z), roundtf(o.w));
        ((float4*)(y + (size_t)row * DMODEL))[t] = orr;
    }

    if (ROUTE) {
        // exact row -> smem, 8 warps compute the 8 expert logits
        ((float4*)rowbuf)[t] = o;
        __syncthreads();
        float sl = 0.0f;
        for (int kk = lane; kk < DMODEL; kk += 32) sl += rowbuf[kk] * gw[kk * NE + warp];
        #pragma unroll
        for (int off = 16; off > 0; off >>= 1) sl += __shfl_down_sync(0xffffffffu, sl, off);
        if (lane == 0) lg[warp] = sl + gb[warp];
        __syncthreads();
        if (t == 0) {
            int i0 = 0; float v0 = lg[0];
            #pragma unroll
            for (int i = 1; i < NE; i++) if (lg[i] > v0) { v0 = lg[i]; i0 = i; }
            int i1 = -1; float v1 = -3.4e38f;
            #pragma unroll
            for (int i = 0; i < NE; i++) if (i != i0 && lg[i] > v1) { v1 = lg[i]; i1 = i; }
            float e1 = expf(v1 - v0);
            float invs = 1.0f / (1.0f + e1);
            float w0 = invs, w1 = e1 * invs;
            int p0 = atomicAdd(&g_cnt[i0], 1);
            g_ptok[i0 * MAXM + p0] = row;
            g_pos[2 * row] = i0 * MAXM + p0;
            g_wgt[2 * row] = w0;
            int p1 = atomicAdd(&g_cnt[i1], 1);
            g_ptok[i1 * MAXM + p1] = row;
            g_pos[2 * row + 1] = i1 * MAXM + p1;
            g_wgt[2 * row + 1] = w1;
        }
    }
}

// ---------------- TF32 tensor-core GEMM (static double-buffer) ----------------
// A is PRE-ROUNDED to tf32 (RNA) by its producer.
#define LDA 20
#define LDB 72

template<int RELU, int ACCUM, int EXPERT, int GATHER, int QKV>
__global__ void __launch_bounds__(256)
tgemm(const float* __restrict__ A,
      const float* __restrict__ W0, const float* __restrict__ Wx1, const float* __restrict__ Wx2,
      const float* __restrict__ B0, const float* __restrict__ Bx1, const float* __restrict__ Bx2,
      float* __restrict__ C0, float* __restrict__ Cx1, float* __restrict__ Cx2,
      int M, int N, int K,
      const int* __restrict__ gather, const int* __restrict__ cnt,
      size_t aStride, size_t cStride)
{
    __shared__ __align__(16) unsigned As[2][128 * LDA];
    __shared__ __align__(16) unsigned Bs[2][16 * LDB];

    int e = EXPERT ? blockIdx.z : 0;
    int Mloc = EXPERT ? cnt[e] : M;
    int mBase = blockIdx.y * 128;
    if (mBase >= Mloc) return;
    int nBase = blockIdx.x * 64;

    const float* W = W0; const float* bias = B0; float* C = C0;
    if (QKV) {
        int z = blockIdx.z;
        if (z == 1)      { W = Wx1; bias = Bx1; C = Cx1; }
        else if (z == 2) { W = Wx2; bias = Bx2; C = Cx2; }
    }
    const float* Ap = A;
    if (EXPERT) {
        W = W0 + (size_t)e * K * N;
        bias = B0 + (size_t)e * N;
        C = C0 + (size_t)e * cStride;
        if (!GATHER) Ap = A + (size_t)e * aStride;
    }

    int tid = threadIdx.x;
    int lane = tid & 31, warp = tid >> 5;
    int wM = (warp & 1) * 64;
    int wN = (warp >> 1) * 16;
    int g = lane >> 2, t = lane & 3;

    int r0 = tid >> 2;
    int r1 = r0 + 64;
    int ac4 = (tid & 3) * 4;
    int m0 = mBase + r0; m0 = m0 < Mloc ? m0 : Mloc - 1;
    int m1 = mBase + r1; m1 = m1 < Mloc ? m1 : Mloc - 1;
    int ar0 = GATHER ? gather[e * MAXM + m0] : m0;
    int ar1 = GATHER ? gather[e * MAXM + m1] : m1;
    const float* pA0 = Ap + (size_t)ar0 * K + ac4;
    const float* pA1 = Ap + (size_t)ar1 * K + ac4;

    int br  = tid >> 4;
    int bc4 = (tid & 15) * 4;
    const float* pB = W + (size_t)br * N + nBase + bc4;

    float acc[4][2][4];
    #pragma unroll
    for (int i = 0; i < 4; i++)
        #pragma unroll
        for (int j = 0; j < 2; j++)
            #pragma unroll
            for (int q = 0; q < 4; q++) acc[i][j][q] = 0.0f;

    float4 sa0 = *(const float4*)pA0;
    float4 sa1 = *(const float4*)pA1;
    float4 sb  = *(const float4*)pB;

    int buf = 0;
    for (int k0 = 0; k0 < K; k0 += 16) {
        unsigned* As_ = As[buf];
        unsigned* Bs_ = Bs[buf];
        *(uint4*)&As_[r0 * LDA + ac4] = *reinterpret_cast<uint4*>(&sa0);
        *(uint4*)&As_[r1 * LDA + ac4] = *reinterpret_cast<uint4*>(&sa1);
        uint4 ub;
        ub.x = f2tf(sb.x); ub.y = f2tf(sb.y); ub.z = f2tf(sb.z); ub.w = f2tf(sb.w);
        *(uint4*)&Bs_[br * LDB + bc4] = ub;
        __syncthreads();

        if (k0 + 16 < K) {
            sa0 = *(const float4*)(pA0 + k0 + 16);
            sa1 = *(const float4*)(pA1 + k0 + 16);
            sb  = *(const float4*)(pB + (size_t)(k0 + 16) * N);
        }

        #pragma unroll
        for (int ks = 0; ks < 2; ks++) {
            unsigned af[4][4], bf[2][2];
            #pragma unroll
            for (int mt = 0; mt < 4; mt++) {
                int base = (wM + mt * 16 + g) * LDA + ks * 8 + t;
                af[mt][0] = As_[base];
                af[mt][1] = As_[base + 8 * LDA];
                af[mt][2] = As_[base + 4];
                af[mt][3] = As_[base + 8 * LDA + 4];
            }
            #pragma unroll
            for (int nt = 0; nt < 2; nt++) {
                int base = (ks * 8 + t) * LDB + wN + nt * 8 + g;
                bf[nt][0] = Bs_[base];
                bf[nt][1] = Bs_[base + 4 * LDB];
            }
            #pragma unroll
            for (int mt = 0; mt < 4; mt++)
                #pragma unroll
                for (int nt = 0; nt < 2; nt++)
                    asm volatile(
                        "mma.sync.aligned.m16n8k8.row.col.f32.tf32.tf32.f32 "
                        "{%0,%1,%2,%3}, {%4,%5,%6,%7}, {%8,%9}, {%0,%1,%2,%3};"
                        : "+f"(acc[mt][nt][0]), "+f"(acc[mt][nt][1]),
                          "+f"(acc[mt][nt][2]), "+f"(acc[mt][nt][3])
                        : "r"(af[mt][0]), "r"(af[mt][1]), "r"(af[mt][2]), "r"(af[mt][3]),
                          "r"(bf[nt][0]), "r"(bf[nt][1]));
        }
        buf ^= 1;
    }

    #pragma unroll
    for (int mt = 0; mt < 4; mt++) {
        #pragma unroll
        for (int half = 0; half < 2; half++) {
            int r = mBase + wM + mt * 16 + g + half * 8;
            if (r < Mloc) {
                #pragma unroll
                for (int nt = 0; nt < 2; nt++) {
                    int col = nBase + wN + nt * 8 + 2 * t;
                    float* cp = C + (size_t)r * N + col;
                    float v0 = acc[mt][nt][half * 2 + 0] + bias[col];
                    float v1 = acc[mt][nt][half * 2 + 1] + bias[col + 1];
                    if (RELU) {
                        v0 = roundtf(fmaxf(v0, 0.0f));
                        v1 = roundtf(fmaxf(v1, 0.0f));
                    }
                    if (ACCUM) { cp[0] += v0; cp[1] += v1; }
                    else       { cp[0] = v0;  cp[1] = v1; }
                }
            }
        }
    }
}

// ---------------- flash attention, 2-query register blocking ----------------
#define QT 32
#define KT 64
#define KVP 68                 // K/V & Q smem row pitch (floats)
#define PP 72                  // P smem row pitch (floats)

__global__ void __launch_bounds__(256)
attn4_kernel(const float* __restrict__ q, const float* __restrict__ k,
             const float* __restrict__ v, const int* __restrict__ abt,
             const float* __restrict__ bias_emb, float* __restrict__ o)
{
    __shared__ float Qs[QT * KVP];
    __shared__ float KVs[KT * KVP];
    __shared__ float Ps[QT * PP];

    int bid = blockIdx.x;
    int qt = bid & 7, h = (bid >> 3) & 15, b = bid >> 7;
    int q0 = qt * QT;
    int t = threadIdx.x;
    int qpair = t >> 4;
    int q2 = qpair * 2;
    int kk = t & 15;
    int sub = t & 7, vhalf = (t >> 3) & 1;

    {
        int r = t >> 3, c = (t & 7) * 8;
        const float* qg = q + (size_t)(b * SEQ + q0 + r) * DMODEL + h * HDIM + c;
        float4 a0 = *(const float4*)qg;
        float4 a1 = *(const float4*)(qg + 4);
        float* dst = Qs + r * KVP + c;
        dst[0] = a0.x * 0.125f; dst[1] = a0.y * 0.125f; dst[2] = a0.z * 0.125f; dst[3] = a0.w * 0.125f;
        dst[4] = a1.x * 0.125f; dst[5] = a1.y * 0.125f; dst[6] = a1.z * 0.125f; dst[7] = a1.w * 0.125f;
    }
    __syncthreads();

    float m0r = -3.4e38f, m1r = -3.4e38f, l0r = 0.0f, l1r = 0.0f;
    float4 oA0 = make_float4(0, 0, 0, 0), oA1 = make_float4(0, 0, 0, 0);
    float4 oB0 = make_float4(0, 0, 0, 0), oB1 = make_float4(0, 0, 0, 0);

    for (int kt = 0; kt < 4; kt++) {
        int k0 = kt * KT;
        {
            int r = t >> 2, c = (t & 3) * 16;
            const float* kg = k + (size_t)(b * SEQ + k0 + r) * DMODEL + h * HDIM + c;
            float4 x0 = *(const float4*)kg;
            float4 x1 = *(const float4*)(kg + 4);
            float4 x2 = *(const float4*)(kg + 8);
            float4 x3 = *(const float4*)(kg + 12);
            float* dst = KVs + r * KVP + c;
            *(float4*)(dst)      = x0;
            *(float4*)(dst + 4)  = x1;
            *(float4*)(dst + 8)  = x2;
            *(float4*)(dst + 12) = x3;
        }
        __syncthreads();

        float acc0[4] = {0, 0, 0, 0}, acc1[4] = {0, 0, 0, 0};
        const float* qrow0 = Qs + q2 * KVP;
        const float* qrow1 = qrow0 + KVP;
        #pragma unroll
        for (int d4 = 0; d4 < 16; d4++) {
            float4 qa = *(const float4*)(qrow0 + d4 * 4);
            float4 qb = *(const float4*)(qrow1 + d4 * 4);
            #pragma unroll
            for (int jj = 0; jj < 4; jj++) {
                float4 kv = *(const float4*)(KVs + (kk + 16 * jj) * KVP + d4 * 4);
                acc0[jj] += qa.x * kv.x + qa.y * kv.y + qa.z * kv.z + qa.w * kv.w;
                acc1[jj] += qb.x * kv.x + qb.y * kv.y + qb.z * kv.z + qb.w * kv.w;
            }
        }
        const int* arow0 = abt + (size_t)(b * SEQ + q0 + q2) * SEQ + k0;
        const int* arow1 = arow0 + SEQ;
        float tm0 = -3.4e38f, tm1 = -3.4e38f;
        #pragma unroll
        for (int jj = 0; jj < 4; jj++) {
            acc0[jj] += bias_emb[arow0[kk + 16 * jj] * NH + h];
            acc1[jj] += bias_emb[arow1[kk + 16 * jj] * NH + h];
            tm0 = fmaxf(tm0, acc0[jj]);
            tm1 = fmaxf(tm1, acc1[jj]);
        }
        #pragma unroll
        for (int off = 8; off > 0; off >>= 1) {
            tm0 = fmaxf(tm0, __shfl_xor_sync(0xffffffffu, tm0, off));
            tm1 = fmaxf(tm1, __shfl_xor_sync(0xffffffffu, tm1, off));
        }
        float mn0 = fmaxf(m0r, tm0), mn1 = fmaxf(m1r, tm1);
        float a0 = expf(m0r - mn0), a1 = expf(m1r - mn1);
        float ts0 = 0.0f, ts1 = 0.0f;
        #pragma unroll
        for (int jj = 0; jj < 4; jj++) {
            float p0 = expf(acc0[jj] - mn0);
            float p1 = expf(acc1[jj] - mn1);
            Ps[q2 * PP + kk + 16 * jj] = p0;
            Ps[(q2 + 1) * PP + kk + 16 * jj] = p1;
            ts0 += p0; ts1 += p1;
        }
        #pragma unroll
        for (int off = 8; off > 0; off >>= 1) {
            ts0 += __shfl_xor_sync(0xffffffffu, ts0, off);
            ts1 += __shfl_xor_sync(0xffffffffu, ts1, off);
        }
        l0r = l0r * a0 + ts0; m0r = mn0;
        l1r = l1r * a1 + ts1; m1r = mn1;
        __syncthreads();

        {
            int r = t >> 2, c = (t & 3) * 16;
            const float* vg = v + (size_t)(b * SEQ + k0 + r) * DMODEL + h * HDIM + c;
            float4 x0 = *(const float4*)vg;
            float4 x1 = *(const float4*)(vg + 4);
            float4 x2 = *(const float4*)(vg + 8);
            float4 x3 = *(const float4*)(vg + 12);
            float* dst = KVs + r * KVP + c;
            *(float4*)(dst)      = x0;
            *(float4*)(dst + 4)  = x1;
            *(float4*)(dst + 8)  = x2;
            *(float4*)(dst + 12) = x3;
        }
        __syncthreads();

        oA0.x *= a0; oA0.y *= a0; oA0.z *= a0; oA0.w *= a0;
        oA1.x *= a0; oA1.y *= a0; oA1.z *= a0; oA1.w *= a0;
        oB0.x *= a1; oB0.y *= a1; oB0.z *= a1; oB0.w *= a1;
        oB1.x *= a1; oB1.y *= a1; oB1.z *= a1; oB1.w *= a1;
        const float* p0 = Ps + q2 * PP + vhalf * 32;
        const float* p1 = p0 + PP;
        #pragma unroll
        for (int j4 = 0; j4 < 8; j4++) {
            float4 pa = *(const float4*)(p0 + j4 * 4);
            float4 pb = *(const float4*)(p1 + j4 * 4);
            float par[4] = {pa.x, pa.y, pa.z, pa.w};
            float pbr[4] = {pb.x, pb.y, pb.z, pb.w};
            #pragma unroll
            for (int u = 0; u < 4; u++) {
                int j = vhalf * 32 + j4 * 4 + u;
                float4 va = *(const float4*)(KVs + j * KVP + sub * 4);
                float4 vb = *(const float4*)(KVs + j * KVP + (sub + 8) * 4);
                float pA = par[u], pB = pbr[u];
                oA0.x += pA * va.x; oA0.y += pA * va.y; oA0.z += pA * va.z; oA0.w += pA * va.w;
                oA1.x += pA * vb.x; oA1.y += pA * vb.y; oA1.z += pA * vb.z; oA1.w += pA * vb.w;
                oB0.x += pB * va.x; oB0.y += pB * va.y; oB0.z += pB * va.z; oB0.w += pB * va.w;
                oB1.x += pB * vb.x; oB1.y += pB * vb.y; oB1.z += pB * vb.z; oB1.w += pB * vb.w;
            }
        }
        __syncthreads();
    }

    #pragma unroll
    for (int c = 0; c < 4; c++) {
        ((float*)&oA0)[c] += __shfl_xor_sync(0xffffffffu, ((float*)&oA0)[c], 8);
        ((float*)&oA1)[c] += __shfl_xor_sync(0xffffffffu, ((float*)&oA1)[c], 8);
        ((float*)&oB0)[c] += __shfl_xor_sync(0xffffffffu, ((float*)&oB0)[c], 8);
        ((float*)&oB1)[c] += __shfl_xor_sync(0xffffffffu, ((float*)&oB1)[c], 8);
    }

    float invq = (vhalf == 0) ? (1.0f / l0r) : (1.0f / l1r);
    float4 w0 = (vhalf == 0) ? oA0 : oB0;
    float4 w1 = (vhalf == 0) ? oA1 : oB1;
    w0.x = roundtf(w0.x * invq); w0.y = roundtf(w0.y * invq);
    w0.z = roundtf(w0.z * invq); w0.w = roundtf(w0.w * invq);
    w1.x = roundtf(w1.x * invq); w1.y = roundtf(w1.y * invq);
    w1.z = roundtf(w1.z * invq); w1.w = roundtf(w1.w * invq);
    float* og = o + (size_t)(b * SEQ + q0 + q2 + vhalf) * DMODEL + h * HDIM;
    *(float4*)(og + sub * 4) = w0;
    *(float4*)(og + 32 + sub * 4) = w1;
}

// ---------------- host orchestration ----------------
extern "C" void kernel_launch(void* const* d_in, const int* in_sizes, int n_in,
                              void* d_out, int out_size)
{
    (void)in_sizes; (void)n_in; (void)out_size;
    const int*   et       = (const int*)d_in[0];
    const int*   xi       = (const int*)d_in[1];
    const int*   abt      = (const int*)d_in[2];
    const float* ent      = (const float*)d_in[3];
    const float* maskemb  = (const float*)d_in[4];
    const float* rel      = (const float*)d_in[5];
    const float* type     = (const float*)d_in[6];
    const float* bias_emb = (const float*)d_in[7];
    const float* ln1g     = (const float*)d_in[8];
    const float* ln1b     = (const float*)d_in[9];
    const float* wq       = (const float*)d_in[10];
    const float* bq       = (const float*)d_in[11];
    const float* wk       = (const float*)d_in[12];
    const float* bk       = (const float*)d_in[13];
    const float* wv       = (const float*)d_in[14];
    const float* bv       = (const float*)d_in[15];
    const float* wo       = (const float*)d_in[16];
    const float* bo       = (const float*)d_in[17];
    const float* ln2g     = (const float*)d_in[18];
    const float* ln2b     = (const float*)d_in[19];
    const float* gw       = (const float*)d_in[20];
    const float* gb       = (const float*)d_in[21];
    const float* w1       = (const float*)d_in[22];
    const float* b1       = (const float*)d_in[23];
    const float* w2       = (const float*)d_in[24];
    const float* b2       = (const float*)d_in[25];
    const float* flng     = (const float*)d_in[26];
    const float* flnb     = (const float*)d_in[27];
    float* out = (float*)d_out;

    float *feat, *xnr, *qb2, *kb2, *vb2, *ob, *hb, *yb;
    int *cntp, *ptokp;
    cudaGetSymbolAddress((void**)&feat,  g_feat);
    cudaGetSymbolAddress((void**)&xnr,   g_xnr);
    cudaGetSymbolAddress((void**)&qb2,   g_q);
    cudaGetSymbolAddress((void**)&kb2,   g_k);
    cudaGetSymbolAddress((void**)&vb2,   g_v);
    cudaGetSymbolAddress((void**)&ob,    g_o);
    cudaGetSymbolAddress((void**)&hb,    g_h);
    cudaGetSymbolAddress((void**)&yb,    g_y2);
    cudaGetSymbolAddress((void**)&cntp,  g_cnt);
    cudaGetSymbolAddress((void**)&ptokp, g_ptok);

    embed_kernel<<<NTOK, 256>>>(et, xi, ent, maskemb, rel, type);

    for (int l = 0; l < 2; l++) {
        const size_t dd = (size_t)DMODEL * DMODEL;
        // 1) LN1 (+combine of previous layer's MoE for l>0) -> xnr; clears g_cnt
        if (l == 0)
            lnf_kernel<0,0,0,1><<<NTOK, 256>>>(feat, ln1g, ln1b, xnr,
                                               (const float*)0, (const float*)0);
        else
            lnf_kernel<1,0,0,1><<<NTOK, 256>>>(feat, ln1g + l * DMODEL, ln1b + l * DMODEL, xnr,
                                               (const float*)0, (const float*)0);
        // 2) fused q,k,v projections
        tgemm<0,0,0,0,1><<<dim3(16, 8, 3), 256>>>(
            xnr, wq + l * dd, wk + l * dd, wv + l * dd,
            bq + l * DMODEL, bk + l * DMODEL, bv + l * DMODEL,
            qb2, kb2, vb2,
            NTOK, DMODEL, DMODEL, (const int*)0, (const int*)0, 0, 0);
        // 3) attention (flash, 2-query register blocking); output pre-rounded
        attn4_kernel<<<NB * NH * (SEQ / QT), 256>>>(
            qb2, kb2, vb2, abt, bias_emb, ob);
        // 4) out proj + residual accumulate
        tgemm<0,1,0,0,0><<<dim3(16, 8), 256>>>(
            ob, wo + l * dd, (const float*)0, (const float*)0,
            bo + l * DMODEL, (const float*)0, (const float*)0,
            feat, (float*)0, (float*)0,
            NTOK, DMODEL, DMODEL, (const int*)0, (const int*)0, 0, 0);
        // 5) LN2 + fused routing -> xnr, g_pos/g_wgt/g_ptok/g_cnt
        lnf_kernel<0,1,0,0><<<NTOK, 256>>>(feat, ln2g + l * DMODEL, ln2b + l * DMODEL, xnr,
                                           gw + (size_t)l * DMODEL * NE, gb + l * NE);
        // 6) expert up-proj + relu (gathered rows of xnr); output pre-rounded
        tgemm<1,0,1,1,0><<<dim3(32, 8, 8), 256>>>(
            xnr, w1 + (size_t)l * NE * DMODEL * DHID, (const float*)0, (const float*)0,
            b1 + (size_t)l * NE * DHID, (const float*)0, (const float*)0,
            hb, (float*)0, (float*)0,
            MAXM, DHID, DMODEL, ptokp, cntp, 0, (size_t)MAXM * DHID);
        // 7) expert down-proj
        tgemm<0,0,1,0,0><<<dim3(16, 8, 8), 256>>>(
            hb, w2 + (size_t)l * NE * DHID * DMODEL, (const float*)0, (const float*)0,
            b2 + (size_t)l * NE * DMODEL, (const float*)0, (const float*)0,
            yb, (float*)0, (float*)0,
            MAXM, DMODEL, DHID, (const int*)0, cntp, (size_t)MAXM * DHID, (size_t)MAXM * DMODEL);
    }

    // final layernorm (+combine of layer-1 MoE) -> exact out
    lnf_kernel<1,0,1,0><<<NTOK, 256>>>(feat, flng, flnb, out,
                                       (const float*)0, (const float*)0);
}

// round 15
// speedup vs baseline: 1.2713x; 1.1247x over previous
#include <cuda_runtime.h>
#include <math.h>

// Problem constants
#define NTOK 1024      // B*S
#define DMODEL 1024
#define NH 16
#define HDIM 64
#define SEQ 256
#define NB 4
#define NE 8
#define DHID 2048
#define MAXM 1024      // max rows per expert

// ---------------- scratch (device globals; no allocation allowed) ----------------
__device__ float g_feat[NTOK * DMODEL];
__device__ float g_xnr[NTOK * DMODEL];    // tf32-rounded LN output (GEMM A)
__device__ float g_q[NTOK * DMODEL];
__device__ float g_k[NTOK * DMODEL];
__device__ float g_v[NTOK * DMODEL];
__device__ float g_o[NTOK * DMODEL];
__device__ float g_h[NE * MAXM * DHID];    // expert hidden (tf32-rounded)
__device__ float g_y2[NE * MAXM * DMODEL]; // expert output
__device__ int   g_cnt[NE];
__device__ int   g_ptok[NE * MAXM];
__device__ int   g_pos[NTOK * 2];
__device__ float g_wgt[NTOK * 2];

__device__ __forceinline__ unsigned f2tf(float f) {
    unsigned u; asm("cvt.rna.tf32.f32 %0, %1;" : "=r"(u) : "f"(f)); return u;
}
__device__ __forceinline__ float roundtf(float f) {
    return __uint_as_float(f2tf(f));
}

// ---------------- embedding ----------------
__global__ void embed_kernel(const int* __restrict__ et, const int* __restrict__ xi,
                             const float* __restrict__ ent, const float* __restrict__ maskemb,
                             const float* __restrict__ rel, const float* __restrict__ type)
{
    int tok = blockIdx.x, t = threadIdx.x;   // 256 threads, 1 float4 each
    int ty = et[tok];
    int xv = xi[tok];
    const float* src;
    if (ty == 0)      src = ent + (size_t)(((unsigned)xv) % 40000u) * DMODEL;
    else if (ty == 1) src = maskemb;
    else              src = rel + (size_t)(((unsigned)xv) % 1000u) * DMODEL;
    float4 s4 = ((const float4*)src)[t];
    float4 t4 = ((const float4*)(type + (size_t)ty * DMODEL))[t];
    float4 r = make_float4(s4.x + t4.x, s4.y + t4.y, s4.z + t4.z, s4.w + t4.w);
    ((float4*)(g_feat + (size_t)tok * DMODEL))[t] = r;
}

// ---------------- fused layernorm (+optional combine / routing / cnt-clear) --------
template<int COMBINE, int ROUTE, int EXACT, int CLEARCNT>
__global__ void __launch_bounds__(256)
lnf_kernel(const float* __restrict__ x, const float* __restrict__ g,
           const float* __restrict__ b, float* __restrict__ y,
           const float* __restrict__ gw, const float* __restrict__ gb)
{
    __shared__ float ws[8], ws2[8], lg[NE];
    __shared__ float rowbuf[DMODEL];

    int row = blockIdx.x, t = threadIdx.x;
    int lane = t & 31, warp = t >> 5;
    if (CLEARCNT && row == 0 && t < NE) g_cnt[t] = 0;

    float4 xv = ((const float4*)(x + (size_t)row * DMODEL))[t];
    if (COMBINE) {
        int p0 = g_pos[2 * row], p1 = g_pos[2 * row + 1];
        float w0 = g_wgt[2 * row], w1 = g_wgt[2 * row + 1];
        float4 a = ((const float4*)(g_y2 + (size_t)p0 * DMODEL))[t];
        float4 c = ((const float4*)(g_y2 + (size_t)p1 * DMODEL))[t];
        xv.x += w0 * a.x + w1 * c.x;
        xv.y += w0 * a.y + w1 * c.y;
        xv.z += w0 * a.z + w1 * c.z;
        xv.w += w0 * a.w + w1 * c.w;
        ((float4*)(g_feat + (size_t)row * DMODEL))[t] = xv;  // residual stream update
    }

    float s = xv.x + xv.y + xv.z + xv.w;
    #pragma unroll
    for (int off = 16; off > 0; off >>= 1) s += __shfl_xor_sync(0xffffffffu, s, off);
    if (lane == 0) ws[warp] = s;
    __syncthreads();
    float m = (ws[0] + ws[1] + ws[2] + ws[3] + ws[4] + ws[5] + ws[6] + ws[7]) * (1.0f / DMODEL);

    float dx = xv.x - m, dy = xv.y - m, dz = xv.z - m, dw = xv.w - m;
    float s2 = dx * dx + dy * dy + dz * dz + dw * dw;
    #pragma unroll
    for (int off = 16; off > 0; off >>= 1) s2 += __shfl_xor_sync(0xffffffffu, s2, off);
    if (lane == 0) ws2[warp] = s2;
    __syncthreads();
    float v = (ws2[0] + ws2[1] + ws2[2] + ws2[3] + ws2[4] + ws2[5] + ws2[6] + ws2[7]) * (1.0f / DMODEL);
    float rs = rsqrtf(v + 1e-5f);

    float4 gv = ((const float4*)g)[t];
    float4 bv = ((const float4*)b)[t];
    float4 o = make_float4(dx * rs * gv.x + bv.x, dy * rs * gv.y + bv.y,
                           dz * rs * gv.z + bv.z, dw * rs * gv.w + bv.w);
    if (EXACT) {
        ((float4*)(y + (size_t)row * DMODEL))[t] = o;
    } else {
        float4 orr = make_float4(roundtf(o.x), roundtf(o.y), roundtf(o.z), roundtf(o.w));
        ((float4*)(y + (size_t)row * DMODEL))[t] = orr;
    }

    if (ROUTE) {
        ((float4*)rowbuf)[t] = o;
        __syncthreads();
        float sl = 0.0f;
        for (int kk = lane; kk < DMODEL; kk += 32) sl += rowbuf[kk] * gw[kk * NE + warp];
        #pragma unroll
        for (int off = 16; off > 0; off >>= 1) sl += __shfl_down_sync(0xffffffffu, sl, off);
        if (lane == 0) lg[warp] = sl + gb[warp];
        __syncthreads();
        if (t == 0) {
            int i0 = 0; float v0 = lg[0];
            #pragma unroll
            for (int i = 1; i < NE; i++) if (lg[i] > v0) { v0 = lg[i]; i0 = i; }
            int i1 = -1; float v1 = -3.4e38f;
            #pragma unroll
            for (int i = 0; i < NE; i++) if (i != i0 && lg[i] > v1) { v1 = lg[i]; i1 = i; }
            float e1 = expf(v1 - v0);
            float invs = 1.0f / (1.0f + e1);
            float w0 = invs, w1 = e1 * invs;
            int p0 = atomicAdd(&g_cnt[i0], 1);
            g_ptok[i0 * MAXM + p0] = row;
            g_pos[2 * row] = i0 * MAXM + p0;
            g_wgt[2 * row] = w0;
            int p1 = atomicAdd(&g_cnt[i1], 1);
            g_ptok[i1 * MAXM + p1] = row;
            g_pos[2 * row + 1] = i1 * MAXM + p1;
            g_wgt[2 * row + 1] = w1;
        }
    }
}

// ---------------- TF32 tensor-core GEMM, 128x64 tile (used for wo) ----------------
#define LDA 20
#define LDB 72

template<int RELU, int ACCUM, int EXPERT, int GATHER, int QKV>
__global__ void __launch_bounds__(256)
tgemm(const float* __restrict__ A,
      const float* __restrict__ W0, const float* __restrict__ Wx1, const float* __restrict__ Wx2,
      const float* __restrict__ B0, const float* __restrict__ Bx1, const float* __restrict__ Bx2,
      float* __restrict__ C0, float* __restrict__ Cx1, float* __restrict__ Cx2,
      int M, int N, int K,
      const int* __restrict__ gather, const int* __restrict__ cnt,
      size_t aStride, size_t cStride)
{
    __shared__ __align__(16) unsigned As[2][128 * LDA];
    __shared__ __align__(16) unsigned Bs[2][16 * LDB];

    int e = EXPERT ? blockIdx.z : 0;
    int Mloc = EXPERT ? cnt[e] : M;
    int mBase = blockIdx.y * 128;
    if (mBase >= Mloc) return;
    int nBase = blockIdx.x * 64;

    const float* W = W0; const float* bias = B0; float* C = C0;
    if (QKV) {
        int z = blockIdx.z;
        if (z == 1)      { W = Wx1; bias = Bx1; C = Cx1; }
        else if (z == 2) { W = Wx2; bias = Bx2; C = Cx2; }
    }
    const float* Ap = A;
    if (EXPERT) {
        W = W0 + (size_t)e * K * N;
        bias = B0 + (size_t)e * N;
        C = C0 + (size_t)e * cStride;
        if (!GATHER) Ap = A + (size_t)e * aStride;
    }

    int tid = threadIdx.x;
    int lane = tid & 31, warp = tid >> 5;
    int wM = (warp & 1) * 64;
    int wN = (warp >> 1) * 16;
    int g = lane >> 2, t = lane & 3;

    int r0 = tid >> 2;
    int r1 = r0 + 64;
    int ac4 = (tid & 3) * 4;
    int m0 = mBase + r0; m0 = m0 < Mloc ? m0 : Mloc - 1;
    int m1 = mBase + r1; m1 = m1 < Mloc ? m1 : Mloc - 1;
    int ar0 = GATHER ? gather[e * MAXM + m0] : m0;
    int ar1 = GATHER ? gather[e * MAXM + m1] : m1;
    const float* pA0 = Ap + (size_t)ar0 * K + ac4;
    const float* pA1 = Ap + (size_t)ar1 * K + ac4;

    int br  = tid >> 4;
    int bc4 = (tid & 15) * 4;
    const float* pB = W + (size_t)br * N + nBase + bc4;

    float acc[4][2][4];
    #pragma unroll
    for (int i = 0; i < 4; i++)
        #pragma unroll
        for (int j = 0; j < 2; j++)
            #pragma unroll
            for (int q = 0; q < 4; q++) acc[i][j][q] = 0.0f;

    float4 sa0 = *(const float4*)pA0;
    float4 sa1 = *(const float4*)pA1;
    float4 sb  = *(const float4*)pB;

    int buf = 0;
    for (int k0 = 0; k0 < K; k0 += 16) {
        unsigned* As_ = As[buf];
        unsigned* Bs_ = Bs[buf];
        *(uint4*)&As_[r0 * LDA + ac4] = *reinterpret_cast<uint4*>(&sa0);
        *(uint4*)&As_[r1 * LDA + ac4] = *reinterpret_cast<uint4*>(&sa1);
        uint4 ub;
        ub.x = f2tf(sb.x); ub.y = f2tf(sb.y); ub.z = f2tf(sb.z); ub.w = f2tf(sb.w);
        *(uint4*)&Bs_[br * LDB + bc4] = ub;
        __syncthreads();

        if (k0 + 16 < K) {
            sa0 = *(const float4*)(pA0 + k0 + 16);
            sa1 = *(const float4*)(pA1 + k0 + 16);
            sb  = *(const float4*)(pB + (size_t)(k0 + 16) * N);
        }

        #pragma unroll
        for (int ks = 0; ks < 2; ks++) {
            unsigned af[4][4], bf[2][2];
            #pragma unroll
            for (int mt = 0; mt < 4; mt++) {
                int base = (wM + mt * 16 + g) * LDA + ks * 8 + t;
                af[mt][0] = As_[base];
                af[mt][1] = As_[base + 8 * LDA];
                af[mt][2] = As_[base + 4];
                af[mt][3] = As_[base + 8 * LDA + 4];
            }
            #pragma unroll
            for (int nt = 0; nt < 2; nt++) {
                int base = (ks * 8 + t) * LDB + wN + nt * 8 + g;
                bf[nt][0] = Bs_[base];
                bf[nt][1] = Bs_[base + 4 * LDB];
            }
            #pragma unroll
            for (int mt = 0; mt < 4; mt++)
                #pragma unroll
                for (int nt = 0; nt < 2; nt++)
                    asm volatile(
                        "mma.sync.aligned.m16n8k8.row.col.f32.tf32.tf32.f32 "
                        "{%0,%1,%2,%3}, {%4,%5,%6,%7}, {%8,%9}, {%0,%1,%2,%3};"
                        : "+f"(acc[mt][nt][0]), "+f"(acc[mt][nt][1]),
                          "+f"(acc[mt][nt][2]), "+f"(acc[mt][nt][3])
                        : "r"(af[mt][0]), "r"(af[mt][1]), "r"(af[mt][2]), "r"(af[mt][3]),
                          "r"(bf[nt][0]), "r"(bf[nt][1]));
        }
        buf ^= 1;
    }

    #pragma unroll
    for (int mt = 0; mt < 4; mt++) {
        #pragma unroll
        for (int half = 0; half < 2; half++) {
            int r = mBase + wM + mt * 16 + g + half * 8;
            if (r < Mloc) {
                #pragma unroll
                for (int nt = 0; nt < 2; nt++) {
                    int col = nBase + wN + nt * 8 + 2 * t;
                    float* cp = C + (size_t)r * N + col;
                    float v0 = acc[mt][nt][half * 2 + 0] + bias[col];
                    float v1 = acc[mt][nt][half * 2 + 1] + bias[col + 1];
                    if (RELU) {
                        v0 = roundtf(fmaxf(v0, 0.0f));
                        v1 = roundtf(fmaxf(v1, 0.0f));
                    }
                    if (ACCUM) { cp[0] += v0; cp[1] += v1; }
                    else       { cp[0] = v0;  cp[1] = v1; }
                }
            }
        }
    }
}

// ---------------- TF32 tensor-core GEMM, 128x128 tile ----------------
// Warp tile 64x32 (4x4 m16n8k8 per ks). 1.5 LDS/mma (vs 2.5) and half the
// barrier epochs per flop. Smem 37.9 KB -> 2 blocks/SM.
#define LDB2 136

template<int RELU, int ACCUM, int EXPERT, int GATHER, int QKV>
__global__ void __launch_bounds__(256)
tgemm2(const float* __restrict__ A,
       const float* __restrict__ W0, const float* __restrict__ Wx1, const float* __restrict__ Wx2,
       const float* __restrict__ B0, const float* __restrict__ Bx1, const float* __restrict__ Bx2,
       float* __restrict__ C0, float* __restrict__ Cx1, float* __restrict__ Cx2,
       int M, int N, int K,
       const int* __restrict__ gather, const int* __restrict__ cnt,
       size_t aStride, size_t cStride)
{
    __shared__ __align__(16) unsigned As[2][128 * LDA];
    __shared__ __align__(16) unsigned Bs[2][16 * LDB2];

    int e = EXPERT ? blockIdx.z : 0;
    int Mloc = EXPERT ? cnt[e] : M;
    int mBase = blockIdx.y * 128;
    if (mBase >= Mloc) return;
    int nBase = blockIdx.x * 128;

    const float* W = W0; const float* bias = B0; float* C = C0;
    if (QKV) {
        int z = blockIdx.z;
        if (z == 1)      { W = Wx1; bias = Bx1; C = Cx1; }
        else if (z == 2) { W = Wx2; bias = Bx2; C = Cx2; }
    }
    const float* Ap = A;
    if (EXPERT) {
        W = W0 + (size_t)e * K * N;
        bias = B0 + (size_t)e * N;
        C = C0 + (size_t)e * cStride;
        if (!GATHER) Ap = A + (size_t)e * aStride;
    }

    int tid = threadIdx.x;
    int lane = tid & 31, warp = tid >> 5;
    int wM = (warp & 1) * 64;       // 2 warps over M
    int wN = (warp >> 1) * 32;      // 4 warps over N
    int g = lane >> 2, t = lane & 3;

    // A staging: identical to tgemm (two rows per thread, float4 along k)
    int r0 = tid >> 2;
    int r1 = r0 + 64;
    int ac4 = (tid & 3) * 4;
    int m0 = mBase + r0; m0 = m0 < Mloc ? m0 : Mloc - 1;
    int m1 = mBase + r1; m1 = m1 < Mloc ? m1 : Mloc - 1;
    int ar0 = GATHER ? gather[e * MAXM + m0] : m0;
    int ar1 = GATHER ? gather[e * MAXM + m1] : m1;
    const float* pA0 = Ap + (size_t)ar0 * K + ac4;
    const float* pA1 = Ap + (size_t)ar1 * K + ac4;

    // B staging: 16 x 128 tile; thread covers (row br, cols bc..bc+3 and bc+64..bc+67)
    int br  = tid >> 4;
    int bc  = (tid & 15) * 4;
    const float* pB = W + (size_t)br * N + nBase + bc;

    float acc[4][4][4];
    #pragma unroll
    for (int i = 0; i < 4; i++)
        #pragma unroll
        for (int j = 0; j < 4; j++)
            #pragma unroll
            for (int q = 0; q < 4; q++) acc[i][j][q] = 0.0f;

    float4 sa0 = *(const float4*)pA0;
    float4 sa1 = *(const float4*)pA1;
    float4 sb0 = *(const float4*)pB;
    float4 sb1 = *(const float4*)(pB + 64);

    int buf = 0;
    for (int k0 = 0; k0 < K; k0 += 16) {
        unsigned* As_ = As[buf];
        unsigned* Bs_ = Bs[buf];
        *(uint4*)&As_[r0 * LDA + ac4] = *reinterpret_cast<uint4*>(&sa0);
        *(uint4*)&As_[r1 * LDA + ac4] = *reinterpret_cast<uint4*>(&sa1);
        uint4 ub0, ub1;
        ub0.x = f2tf(sb0.x); ub0.y = f2tf(sb0.y); ub0.z = f2tf(sb0.z); ub0.w = f2tf(sb0.w);
        ub1.x = f2tf(sb1.x); ub1.y = f2tf(sb1.y); ub1.z = f2tf(sb1.z); ub1.w = f2tf(sb1.w);
        *(uint4*)&Bs_[br * LDB2 + bc] = ub0;
        *(uint4*)&Bs_[br * LDB2 + bc + 64] = ub1;
        __syncthreads();

        if (k0 + 16 < K) {
            sa0 = *(const float4*)(pA0 + k0 + 16);
            sa1 = *(const float4*)(pA1 + k0 + 16);
            sb0 = *(const float4*)(pB + (size_t)(k0 + 16) * N);
            sb1 = *(const float4*)(pB + (size_t)(k0 + 16) * N + 64);
        }

        #pragma unroll
        for (int ks = 0; ks < 2; ks++) {
            unsigned af[4][4], bf[4][2];
            #pragma unroll
            for (int mt = 0; mt < 4; mt++) {
                int base = (wM + mt * 16 + g) * LDA + ks * 8 + t;
                af[mt][0] = As_[base];
                af[mt][1] = As_[base + 8 * LDA];
                af[mt][2] = As_[base + 4];
                af[mt][3] = As_[base + 8 * LDA + 4];
            }
            #pragma unroll
            for (int nt = 0; nt < 4; nt++) {
                int base = (ks * 8 + t) * LDB2 + wN + nt * 8 + g;
                bf[nt][0] = Bs_[base];
                bf[nt][1] = Bs_[base + 4 * LDB2];
            }
            #pragma unroll
            for (int mt = 0; mt < 4; mt++)
                #pragma unroll
                for (int nt = 0; nt < 4; nt++)
                    asm volatile(
                        "mma.sync.aligned.m16n8k8.row.col.f32.tf32.tf32.f32 "
                        "{%0,%1,%2,%3}, {%4,%5,%6,%7}, {%8,%9}, {%0,%1,%2,%3};"
                        : "+f"(acc[mt][nt][0]), "+f"(acc[mt][nt][1]),
                          "+f"(acc[mt][nt][2]), "+f"(acc[mt][nt][3])
                        : "r"(af[mt][0]), "r"(af[mt][1]), "r"(af[mt][2]), "r"(af[mt][3]),
                          "r"(bf[nt][0]), "r"(bf[nt][1]));
        }
        buf ^= 1;
    }

    #pragma unroll
    for (int mt = 0; mt < 4; mt++) {
        #pragma unroll
        for (int half = 0; half < 2; half++) {
            int r = mBase + wM + mt * 16 + g + half * 8;
            if (r < Mloc) {
                #pragma unroll
                for (int nt = 0; nt < 4; nt++) {
                    int col = nBase + wN + nt * 8 + 2 * t;
                    float* cp = C + (size_t)r * N + col;
                    float v0 = acc[mt][nt][half * 2 + 0] + bias[col];
                    float v1 = acc[mt][nt][half * 2 + 1] + bias[col + 1];
                    if (RELU) {
                        v0 = roundtf(fmaxf(v0, 0.0f));
                        v1 = roundtf(fmaxf(v1, 0.0f));
                    }
                    if (ACCUM) { cp[0] += v0; cp[1] += v1; }
                    else       { cp[0] = v0;  cp[1] = v1; }
                }
            }
        }
    }
}

// ---------------- flash attention, 2-query register blocking ----------------
#define QT 32
#define KT 64
#define KVP 68                 // K/V & Q smem row pitch (floats)
#define PP 72                  // P smem row pitch (floats)

__global__ void __launch_bounds__(256)
attn4_kernel(const float* __restrict__ q, const float* __restrict__ k,
             const float* __restrict__ v, const int* __restrict__ abt,
             const float* __restrict__ bias_emb, float* __restrict__ o)
{
    __shared__ float Qs[QT * KVP];
    __shared__ float KVs[KT * KVP];
    __shared__ float Ps[QT * PP];

    int bid = blockIdx.x;
    int qt = bid & 7, h = (bid >> 3) & 15, b = bid >> 7;
    int q0 = qt * QT;
    int t = threadIdx.x;
    int qpair = t >> 4;
    int q2 = qpair * 2;
    int kk = t & 15;
    int sub = t & 7, vhalf = (t >> 3) & 1;

    {
        int r = t >> 3, c = (t & 7) * 8;
        const float* qg = q + (size_t)(b * SEQ + q0 + r) * DMODEL + h * HDIM + c;
        float4 a0 = *(const float4*)qg;
        float4 a1 = *(const float4*)(qg + 4);
        float* dst = Qs + r * KVP + c;
        dst[0] = a0.x * 0.125f; dst[1] = a0.y * 0.125f; dst[2] = a0.z * 0.125f; dst[3] = a0.w * 0.125f;
        dst[4] = a1.x * 0.125f; dst[5] = a1.y * 0.125f; dst[6] = a1.z * 0.125f; dst[7] = a1.w * 0.125f;
    }
    __syncthreads();

    float m0r = -3.4e38f, m1r = -3.4e38f, l0r = 0.0f, l1r = 0.0f;
    float4 oA0 = make_float4(0, 0, 0, 0), oA1 = make_float4(0, 0, 0, 0);
    float4 oB0 = make_float4(0, 0, 0, 0), oB1 = make_float4(0, 0, 0, 0);

    for (int kt = 0; kt < 4; kt++) {
        int k0 = kt * KT;
        {
            int r = t >> 2, c = (t & 3) * 16;
            const float* kg = k + (size_t)(b * SEQ + k0 + r) * DMODEL + h * HDIM + c;
            float4 x0 = *(const float4*)kg;
            float4 x1 = *(const float4*)(kg + 4);
            float4 x2 = *(const float4*)(kg + 8);
            float4 x3 = *(const float4*)(kg + 12);
            float* dst = KVs + r * KVP + c;
            *(float4*)(dst)      = x0;
            *(float4*)(dst + 4)  = x1;
            *(float4*)(dst + 8)  = x2;
            *(float4*)(dst + 12) = x3;
        }
        __syncthreads();

        float acc0[4] = {0, 0, 0, 0}, acc1[4] = {0, 0, 0, 0};
        const float* qrow0 = Qs + q2 * KVP;
        const float* qrow1 = qrow0 + KVP;
        #pragma unroll
        for (int d4 = 0; d4 < 16; d4++) {
            float4 qa = *(const float4*)(qrow0 + d4 * 4);
            float4 qb = *(const float4*)(qrow1 + d4 * 4);
            #pragma unroll
            for (int jj = 0; jj < 4; jj++) {
                float4 kv = *(const float4*)(KVs + (kk + 16 * jj) * KVP + d4 * 4);
                acc0[jj] += qa.x * kv.x + qa.y * kv.y + qa.z * kv.z + qa.w * kv.w;
                acc1[jj] += qb.x * kv.x + qb.y * kv.y + qb.z * kv.z + qb.w * kv.w;
            }
        }
        const int* arow0 = abt + (size_t)(b * SEQ + q0 + q2) * SEQ + k0;
        const int* arow1 = arow0 + SEQ;
        float tm0 = -3.4e38f, tm1 = -3.4e38f;
        #pragma unroll
        for (int jj = 0; jj < 4; jj++) {
            acc0[jj] += bias_emb[arow0[kk + 16 * jj] * NH + h];
            acc1[jj] += bias_emb[arow1[kk + 16 * jj] * NH + h];
            tm0 = fmaxf(tm0, acc0[jj]);
            tm1 = fmaxf(tm1, acc1[jj]);
        }
        #pragma unroll
        for (int off = 8; off > 0; off >>= 1) {
            tm0 = fmaxf(tm0, __shfl_xor_sync(0xffffffffu, tm0, off));
            tm1 = fmaxf(tm1, __shfl_xor_sync(0xffffffffu, tm1, off));
        }
        float mn0 = fmaxf(m0r, tm0), mn1 = fmaxf(m1r, tm1);
        float a0 = expf(m0r - mn0), a1 = expf(m1r - mn1);
        float ts0 = 0.0f, ts1 = 0.0f;
        #pragma unroll
        for (int jj = 0; jj < 4; jj++) {
            float p0 = expf(acc0[jj] - mn0);
            float p1 = expf(acc1[jj] - mn1);
            Ps[q2 * PP + kk + 16 * jj] = p0;
            Ps[(q2 + 1) * PP + kk + 16 * jj] = p1;
            ts0 += p0; ts1 += p1;
        }
        #pragma unroll
        for (int off = 8; off > 0; off >>= 1) {
            ts0 += __shfl_xor_sync(0xffffffffu, ts0, off);
            ts1 += __shfl_xor_sync(0xffffffffu, ts1, off);
        }
        l0r = l0r * a0 + ts0; m0r = mn0;
        l1r = l1r * a1 + ts1; m1r = mn1;
        __syncthreads();

        {
            int r = t >> 2, c = (t & 3) * 16;
            const float* vg = v + (size_t)(b * SEQ + k0 + r) * DMODEL + h * HDIM + c;
            float4 x0 = *(const float4*)vg;
            float4 x1 = *(const float4*)(vg + 4);
            float4 x2 = *(const float4*)(vg + 8);
            float4 x3 = *(const float4*)(vg + 12);
            float* dst = KVs + r * KVP + c;
            *(float4*)(dst)      = x0;
            *(float4*)(dst + 4)  = x1;
            *(float4*)(dst + 8)  = x2;
            *(float4*)(dst + 12) = x3;
        }
        __syncthreads();

        oA0.x *= a0; oA0.y *= a0; oA0.z *= a0; oA0.w *= a0;
        oA1.x *= a0; oA1.y *= a0; oA1.z *= a0; oA1.w *= a0;
        oB0.x *= a1; oB0.y *= a1; oB0.z *= a1; oB0.w *= a1;
        oB1.x *= a1; oB1.y *= a1; oB1.z *= a1; oB1.w *= a1;
        const float* p0 = Ps + q2 * PP + vhalf * 32;
        const float* p1 = p0 + PP;
        #pragma unroll
        for (int j4 = 0; j4 < 8; j4++) {
            float4 pa = *(const float4*)(p0 + j4 * 4);
            float4 pb = *(const float4*)(p1 + j4 * 4);
            float par[4] = {pa.x, pa.y, pa.z, pa.w};
            float pbr[4] = {pb.x, pb.y, pb.z, pb.w};
            #pragma unroll
            for (int u = 0; u < 4; u++) {
                int j = vhalf * 32 + j4 * 4 + u;
                float4 va = *(const float4*)(KVs + j * KVP + sub * 4);
                float4 vb = *(const float4*)(KVs + j * KVP + (sub + 8) * 4);
                float pA = par[u], pB = pbr[u];
                oA0.x += pA * va.x; oA0.y += pA * va.y; oA0.z += pA * va.z; oA0.w += pA * va.w;
                oA1.x += pA * vb.x; oA1.y += pA * vb.y; oA1.z += pA * vb.z; oA1.w += pA * vb.w;
                oB0.x += pB * va.x; oB0.y += pB * va.y; oB0.z += pB * va.z; oB0.w += pB * va.w;
                oB1.x += pB * vb.x; oB1.y += pB * vb.y; oB1.z += pB * vb.z; oB1.w += pB * vb.w;
            }
        }
        __syncthreads();
    }

    #pragma unroll
    for (int c = 0; c < 4; c++) {
        ((float*)&oA0)[c] += __shfl_xor_sync(0xffffffffu, ((float*)&oA0)[c], 8);
        ((float*)&oA1)[c] += __shfl_xor_sync(0xffffffffu, ((float*)&oA1)[c], 8);
        ((float*)&oB0)[c] += __shfl_xor_sync(0xffffffffu, ((float*)&oB0)[c], 8);
        ((float*)&oB1)[c] += __shfl_xor_sync(0xffffffffu, ((float*)&oB1)[c], 8);
    }

    float invq = (vhalf == 0) ? (1.0f / l0r) : (1.0f / l1r);
    float4 w0 = (vhalf == 0) ? oA0 : oB0;
    float4 w1 = (vhalf == 0) ? oA1 : oB1;
    w0.x = roundtf(w0.x * invq); w0.y = roundtf(w0.y * invq);
    w0.z = roundtf(w0.z * invq); w0.w = roundtf(w0.w * invq);
    w1.x = roundtf(w1.x * invq); w1.y = roundtf(w1.y * invq);
    w1.z = roundtf(w1.z * invq); w1.w = roundtf(w1.w * invq);
    float* og = o + (size_t)(b * SEQ + q0 + q2 + vhalf) * DMODEL + h * HDIM;
    *(float4*)(og + sub * 4) = w0;
    *(float4*)(og + 32 + sub * 4) = w1;
}

// ---------------- host orchestration ----------------
extern "C" void kernel_launch(void* const* d_in, const int* in_sizes, int n_in,
                              void* d_out, int out_size)
{
    (void)in_sizes; (void)n_in; (void)out_size;
    const int*   et       = (const int*)d_in[0];
    const int*   xi       = (const int*)d_in[1];
    const int*   abt      = (const int*)d_in[2];
    const float* ent      = (const float*)d_in[3];
    const float* maskemb  = (const float*)d_in[4];
    const float* rel      = (const float*)d_in[5];
    const float* type     = (const float*)d_in[6];
    const float* bias_emb = (const float*)d_in[7];
    const float* ln1g     = (const float*)d_in[8];
    const float* ln1b     = (const float*)d_in[9];
    const float* wq       = (const float*)d_in[10];
    const float* bq       = (const float*)d_in[11];
    const float* wk       = (const float*)d_in[12];
    const float* bk       = (const float*)d_in[13];
    const float* wv       = (const float*)d_in[14];
    const float* bv       = (const float*)d_in[15];
    const float* wo       = (const float*)d_in[16];
    const float* bo       = (const float*)d_in[17];
    const float* ln2g     = (const float*)d_in[18];
    const float* ln2b     = (const float*)d_in[19];
    const float* gw       = (const float*)d_in[20];
    const float* gb       = (const float*)d_in[21];
    const float* w1       = (const float*)d_in[22];
    const float* b1       = (const float*)d_in[23];
    const float* w2       = (const float*)d_in[24];
    const float* b2       = (const float*)d_in[25];
    const float* flng     = (const float*)d_in[26];
    const float* flnb     = (const float*)d_in[27];
    float* out = (float*)d_out;

    float *feat, *xnr, *qb2, *kb2, *vb2, *ob, *hb, *yb;
    int *cntp, *ptokp;
    cudaGetSymbolAddress((void**)&feat,  g_feat);
    cudaGetSymbolAddress((void**)&xnr,   g_xnr);
    cudaGetSymbolAddress((void**)&qb2,   g_q);
    cudaGetSymbolAddress((void**)&kb2,   g_k);
    cudaGetSymbolAddress((void**)&vb2,   g_v);
    cudaGetSymbolAddress((void**)&ob,    g_o);
    cudaGetSymbolAddress((void**)&hb,    g_h);
    cudaGetSymbolAddress((void**)&yb,    g_y2);
    cudaGetSymbolAddress((void**)&cntp,  g_cnt);
    cudaGetSymbolAddress((void**)&ptokp, g_ptok);

    embed_kernel<<<NTOK, 256>>>(et, xi, ent, maskemb, rel, type);

    for (int l = 0; l < 2; l++) {
        const size_t dd = (size_t)DMODEL * DMODEL;
        // 1) LN1 (+combine of previous layer's MoE for l>0) -> xnr; clears g_cnt
        if (l == 0)
            lnf_kernel<0,0,0,1><<<NTOK, 256>>>(feat, ln1g, ln1b, xnr,
                                               (const float*)0, (const float*)0);
        else
            lnf_kernel<1,0,0,1><<<NTOK, 256>>>(feat, ln1g + l * DMODEL, ln1b + l * DMODEL, xnr,
                                               (const float*)0, (const float*)0);
        // 2) fused q,k,v projections (128x128 tiles: 192 blocks)
        tgemm2<0,0,0,0,1><<<dim3(8, 8, 3), 256>>>(
            xnr, wq + l * dd, wk + l * dd, wv + l * dd,
            bq + l * DMODEL, bk + l * DMODEL, bv + l * DMODEL,
            qb2, kb2, vb2,
            NTOK, DMODEL, DMODEL, (const int*)0, (const int*)0, 0, 0);
        // 3) attention (flash, 2-query register blocking); output pre-rounded
        attn4_kernel<<<NB * NH * (SEQ / QT), 256>>>(
            qb2, kb2, vb2, abt, bias_emb, ob);
        // 4) out proj + residual accumulate (64-wide tiles: 128 blocks)
        tgemm<0,1,0,0,0><<<dim3(16, 8), 256>>>(
            ob, wo + l * dd, (const float*)0, (const float*)0,
            bo + l * DMODEL, (const float*)0, (const float*)0,
            feat, (float*)0, (float*)0,
            NTOK, DMODEL, DMODEL, (const int*)0, (const int*)0, 0, 0);
        // 5) LN2 + fused routing -> xnr, g_pos/g_wgt/g_ptok/g_cnt
        lnf_kernel<0,1,0,0><<<NTOK, 256>>>(feat, ln2g + l * DMODEL, ln2b + l * DMODEL, xnr,
                                           gw + (size_t)l * DMODEL * NE, gb + l * NE);
        // 6) expert up-proj + relu (gathered rows of xnr); output pre-rounded
        tgemm2<1,0,1,1,0><<<dim3(16, 8, 8), 256>>>(
            xnr, w1 + (size_t)l * NE * DMODEL * DHID, (const float*)0, (const float*)0,
            b1 + (size_t)l * NE * DHID, (const float*)0, (const float*)0,
            hb, (float*)0, (float*)0,
            MAXM, DHID, DMODEL, ptokp, cntp, 0, (size_t)MAXM * DHID);
        // 7) expert down-proj
        tgemm2<0,0,1,0,0><<<dim3(8, 8, 8), 256>>>(
            hb, w2 + (size_t)l * NE * DHID * DMODEL, (const float*)0, (const float*)0,
            b2 + (size_t)l * NE * DMODEL, (const float*)0, (const float*)0,
            yb, (float*)0, (float*)0,
            MAXM, DMODEL, DHID, (const int*)0, cntp, (size_t)MAXM * DHID, (size_t)MAXM * DMODEL);
    }

    // final layernorm (+combine of layer-1 MoE) -> exact out
    lnf_kernel<1,0,1,0><<<NTOK, 256>>>(feat, flng, flnb, out,
                                       (const float*)0, (const float*)0);
}

// round 16
// speedup vs baseline: 1.2920x; 1.0163x over previous
#include <cuda_runtime.h>
#include <math.h>

// Problem constants
#define NTOK 1024      // B*S
#define DMODEL 1024
#define NH 16
#define HDIM 64
#define SEQ 256
#define NB 4
#define NE 8
#define DHID 2048
#define MAXM 1024      // max rows per expert

// ---------------- scratch (device globals; no allocation allowed) ----------------
__device__ float g_feat[NTOK * DMODEL];
__device__ float g_xnr[NTOK * DMODEL];    // tf32-rounded LN output (GEMM A)
__device__ float g_q[NTOK * DMODEL];
__device__ float g_k[NTOK * DMODEL];
__device__ float g_v[NTOK * DMODEL];
__device__ float g_o[NTOK * DMODEL];
__device__ float g_h[NE * MAXM * DHID];    // expert hidden (tf32-rounded)
__device__ float g_y2[NE * MAXM * DMODEL]; // expert output
__device__ int   g_cnt[NE];
__device__ int   g_ptok[NE * MAXM];
__device__ int   g_pos[NTOK * 2];
__device__ float g_wgt[NTOK * 2];

__device__ __forceinline__ unsigned f2tf(float f) {
    unsigned u; asm("cvt.rna.tf32.f32 %0, %1;" : "=r"(u) : "f"(f)); return u;
}
__device__ __forceinline__ float roundtf(float f) {
    return __uint_as_float(f2tf(f));
}
__device__ __forceinline__ void cpa16(float* dst_smem, const float* src) {
    unsigned d = (unsigned)__cvta_generic_to_shared(dst_smem);
    asm volatile("cp.async.cg.shared.global [%0], [%1], 16;\n" :: "r"(d), "l"(src));
}
__device__ __forceinline__ void cp_commit() {
    asm volatile("cp.async.commit_group;\n" ::: "memory");
}
template<int N>
__device__ __forceinline__ void cp_wait() {
    asm volatile("cp.async.wait_group %0;\n" :: "n"(N) : "memory");
}

// ---------------- fused embed + LN1 (layer 0) ----------------
// Computes token embedding, writes the residual stream (g_feat), then LN ->
// tf32-rounded yr. Also clears the MoE counters. Same reduction/rounding as lnf.
__global__ void __launch_bounds__(256)
embed_ln_kernel(const int* __restrict__ et, const int* __restrict__ xi,
                const float* __restrict__ ent, const float* __restrict__ maskemb,
                const float* __restrict__ rel, const float* __restrict__ type,
                const float* __restrict__ g, const float* __restrict__ b,
                float* __restrict__ yr)
{
    __shared__ float ws[8], ws2[8];
    int row = blockIdx.x, t = threadIdx.x;
    int lane = t & 31, warp = t >> 5;
    if (row == 0 && t < NE) g_cnt[t] = 0;

    int ty = et[row];
    int xvi = xi[row];
    const float* src;
    if (ty == 0)      src = ent + (size_t)(((unsigned)xvi) % 40000u) * DMODEL;
    else if (ty == 1) src = maskemb;
    else              src = rel + (size_t)(((unsigned)xvi) % 1000u) * DMODEL;
    float4 s4 = ((const float4*)src)[t];
    float4 t4 = ((const float4*)(type + (size_t)ty * DMODEL))[t];
    float4 xv = make_float4(s4.x + t4.x, s4.y + t4.y, s4.z + t4.z, s4.w + t4.w);
    ((float4*)(g_feat + (size_t)row * DMODEL))[t] = xv;

    float s = xv.x + xv.y + xv.z + xv.w;
    #pragma unroll
    for (int off = 16; off > 0; off >>= 1) s += __shfl_xor_sync(0xffffffffu, s, off);
    if (lane == 0) ws[warp] = s;
    __syncthreads();
    float m = (ws[0] + ws[1] + ws[2] + ws[3] + ws[4] + ws[5] + ws[6] + ws[7]) * (1.0f / DMODEL);

    float dx = xv.x - m, dy = xv.y - m, dz = xv.z - m, dw = xv.w - m;
    float s2 = dx * dx + dy * dy + dz * dz + dw * dw;
    #pragma unroll
    for (int off = 16; off > 0; off >>= 1) s2 += __shfl_xor_sync(0xffffffffu, s2, off);
    if (lane == 0) ws2[warp] = s2;
    __syncthreads();
    float v = (ws2[0] + ws2[1] + ws2[2] + ws2[3] + ws2[4] + ws2[5] + ws2[6] + ws2[7]) * (1.0f / DMODEL);
    float rs = rsqrtf(v + 1e-5f);

    float4 gv = ((const float4*)g)[t];
    float4 bv = ((const float4*)b)[t];
    float4 o = make_float4(dx * rs * gv.x + bv.x, dy * rs * gv.y + bv.y,
                           dz * rs * gv.z + bv.z, dw * rs * gv.w + bv.w);
    float4 orr = make_float4(roundtf(o.x), roundtf(o.y), roundtf(o.z), roundtf(o.w));
    ((float4*)(yr + (size_t)row * DMODEL))[t] = orr;
}

// ---------------- fused layernorm (+optional combine / routing / cnt-clear) --------
template<int COMBINE, int ROUTE, int EXACT, int CLEARCNT>
__global__ void __launch_bounds__(256)
lnf_kernel(const float* __restrict__ x, const float* __restrict__ g,
           const float* __restrict__ b, float* __restrict__ y,
           const float* __restrict__ gw, const float* __restrict__ gb)
{
    __shared__ float ws[8], ws2[8], lg[NE];
    __shared__ float rowbuf[DMODEL];

    int row = blockIdx.x, t = threadIdx.x;
    int lane = t & 31, warp = t >> 5;
    if (CLEARCNT && row == 0 && t < NE) g_cnt[t] = 0;

    float4 xv = ((const float4*)(x + (size_t)row * DMODEL))[t];
    if (COMBINE) {
        int p0 = g_pos[2 * row], p1 = g_pos[2 * row + 1];
        float w0 = g_wgt[2 * row], w1 = g_wgt[2 * row + 1];
        float4 a = ((const float4*)(g_y2 + (size_t)p0 * DMODEL))[t];
        float4 c = ((const float4*)(g_y2 + (size_t)p1 * DMODEL))[t];
        xv.x += w0 * a.x + w1 * c.x;
        xv.y += w0 * a.y + w1 * c.y;
        xv.z += w0 * a.z + w1 * c.z;
        xv.w += w0 * a.w + w1 * c.w;
        ((float4*)(g_feat + (size_t)row * DMODEL))[t] = xv;  // residual stream update
    }

    float s = xv.x + xv.y + xv.z + xv.w;
    #pragma unroll
    for (int off = 16; off > 0; off >>= 1) s += __shfl_xor_sync(0xffffffffu, s, off);
    if (lane == 0) ws[warp] = s;
    __syncthreads();
    float m = (ws[0] + ws[1] + ws[2] + ws[3] + ws[4] + ws[5] + ws[6] + ws[7]) * (1.0f / DMODEL);

    float dx = xv.x - m, dy = xv.y - m, dz = xv.z - m, dw = xv.w - m;
    float s2 = dx * dx + dy * dy + dz * dz + dw * dw;
    #pragma unroll
    for (int off = 16; off > 0; off >>= 1) s2 += __shfl_xor_sync(0xffffffffu, s2, off);
    if (lane == 0) ws2[warp] = s2;
    __syncthreads();
    float v = (ws2[0] + ws2[1] + ws2[2] + ws2[3] + ws2[4] + ws2[5] + ws2[6] + ws2[7]) * (1.0f / DMODEL);
    float rs = rsqrtf(v + 1e-5f);

    float4 gv = ((const float4*)g)[t];
    float4 bv = ((const float4*)b)[t];
    float4 o = make_float4(dx * rs * gv.x + bv.x, dy * rs * gv.y + bv.y,
                           dz * rs * gv.z + bv.z, dw * rs * gv.w + bv.w);
    if (EXACT) {
        ((float4*)(y + (size_t)row * DMODEL))[t] = o;
    } else {
        float4 orr = make_float4(roundtf(o.x), roundtf(o.y), roundtf(o.z), roundtf(o.w));
        ((float4*)(y + (size_t)row * DMODEL))[t] = orr;
    }

    if (ROUTE) {
        ((float4*)rowbuf)[t] = o;
        __syncthreads();
        float sl = 0.0f;
        for (int kk = lane; kk < DMODEL; kk += 32) sl += rowbuf[kk] * gw[kk * NE + warp];
        #pragma unroll
        for (int off = 16; off > 0; off >>= 1) sl += __shfl_down_sync(0xffffffffu, sl, off);
        if (lane == 0) lg[warp] = sl + gb[warp];
        __syncthreads();
        if (t == 0) {
            int i0 = 0; float v0 = lg[0];
            #pragma unroll
            for (int i = 1; i < NE; i++) if (lg[i] > v0) { v0 = lg[i]; i0 = i; }
            int i1 = -1; float v1 = -3.4e38f;
            #pragma unroll
            for (int i = 0; i < NE; i++) if (i != i0 && lg[i] > v1) { v1 = lg[i]; i1 = i; }
            float e1 = expf(v1 - v0);
            float invs = 1.0f / (1.0f + e1);
            float w0 = invs, w1 = e1 * invs;
            int p0 = atomicAdd(&g_cnt[i0], 1);
            g_ptok[i0 * MAXM + p0] = row;
            g_pos[2 * row] = i0 * MAXM + p0;
            g_wgt[2 * row] = w0;
            int p1 = atomicAdd(&g_cnt[i1], 1);
            g_ptok[i1 * MAXM + p1] = row;
            g_pos[2 * row + 1] = i1 * MAXM + p1;
            g_wgt[2 * row + 1] = w1;
        }
    }
}

// ---------------- TF32 tensor-core GEMM, 128x64 tile (used for wo) ----------------
#define LDA 20
#define LDB 72

template<int RELU, int ACCUM, int EXPERT, int GATHER, int QKV>
__global__ void __launch_bounds__(256)
tgemm(const float* __restrict__ A,
      const float* __restrict__ W0, const float* __restrict__ Wx1, const float* __restrict__ Wx2,
      const float* __restrict__ B0, const float* __restrict__ Bx1, const float* __restrict__ Bx2,
      float* __restrict__ C0, float* __restrict__ Cx1, float* __restrict__ Cx2,
      int M, int N, int K,
      const int* __restrict__ gather, const int* __restrict__ cnt,
      size_t aStride, size_t cStride)
{
    __shared__ __align__(16) unsigned As[2][128 * LDA];
    __shared__ __align__(16) unsigned Bs[2][16 * LDB];

    int e = EXPERT ? blockIdx.z : 0;
    int Mloc = EXPERT ? cnt[e] : M;
    int mBase = blockIdx.y * 128;
    if (mBase >= Mloc) return;
    int nBase = blockIdx.x * 64;

    const float* W = W0; const float* bias = B0; float* C = C0;
    if (QKV) {
        int z = blockIdx.z;
        if (z == 1)      { W = Wx1; bias = Bx1; C = Cx1; }
        else if (z == 2) { W = Wx2; bias = Bx2; C = Cx2; }
    }
    const float* Ap = A;
    if (EXPERT) {
        W = W0 + (size_t)e * K * N;
        bias = B0 + (size_t)e * N;
        C = C0 + (size_t)e * cStride;
        if (!GATHER) Ap = A + (size_t)e * aStride;
    }

    int tid = threadIdx.x;
    int lane = tid & 31, warp = tid >> 5;
    int wM = (warp & 1) * 64;
    int wN = (warp >> 1) * 16;
    int g = lane >> 2, t = lane & 3;

    int r0 = tid >> 2;
    int r1 = r0 + 64;
    int ac4 = (tid & 3) * 4;
    int m0 = mBase + r0; m0 = m0 < Mloc ? m0 : Mloc - 1;
    int m1 = mBase + r1; m1 = m1 < Mloc ? m1 : Mloc - 1;
    int ar0 = GATHER ? gather[e * MAXM + m0] : m0;
    int ar1 = GATHER ? gather[e * MAXM + m1] : m1;
    const float* pA0 = Ap + (size_t)ar0 * K + ac4;
    const float* pA1 = Ap + (size_t)ar1 * K + ac4;

    int br  = tid >> 4;
    int bc4 = (tid & 15) * 4;
    const float* pB = W + (size_t)br * N + nBase + bc4;

    float acc[4][2][4];
    #pragma unroll
    for (int i = 0; i < 4; i++)
        #pragma unroll
        for (int j = 0; j < 2; j++)
            #pragma unroll
            for (int q = 0; q < 4; q++) acc[i][j][q] = 0.0f;

    float4 sa0 = *(const float4*)pA0;
    float4 sa1 = *(const float4*)pA1;
    float4 sb  = *(const float4*)pB;

    int buf = 0;
    for (int k0 = 0; k0 < K; k0 += 16) {
        unsigned* As_ = As[buf];
        unsigned* Bs_ = Bs[buf];
        *(uint4*)&As_[r0 * LDA + ac4] = *reinterpret_cast<uint4*>(&sa0);
        *(uint4*)&As_[r1 * LDA + ac4] = *reinterpret_cast<uint4*>(&sa1);
        uint4 ub;
        ub.x = f2tf(sb.x); ub.y = f2tf(sb.y); ub.z = f2tf(sb.z); ub.w = f2tf(sb.w);
        *(uint4*)&Bs_[br * LDB + bc4] = ub;
        __syncthreads();

        if (k0 + 16 < K) {
            sa0 = *(const float4*)(pA0 + k0 + 16);
            sa1 = *(const float4*)(pA1 + k0 + 16);
            sb  = *(const float4*)(pB + (size_t)(k0 + 16) * N);
        }

        #pragma unroll
        for (int ks = 0; ks < 2; ks++) {
            unsigned af[4][4], bf[2][2];
            #pragma unroll
            for (int mt = 0; mt < 4; mt++) {
                int base = (wM + mt * 16 + g) * LDA + ks * 8 + t;
                af[mt][0] = As_[base];
                af[mt][1] = As_[base + 8 * LDA];
                af[mt][2] = As_[base + 4];
                af[mt][3] = As_[base + 8 * LDA + 4];
            }
            #pragma unroll
            for (int nt = 0; nt < 2; nt++) {
                int base = (ks * 8 + t) * LDB + wN + nt * 8 + g;
                bf[nt][0] = Bs_[base];
                bf[nt][1] = Bs_[base + 4 * LDB];
            }
            #pragma unroll
            for (int mt = 0; mt < 4; mt++)
                #pragma unroll
                for (int nt = 0; nt < 2; nt++)
                    asm volatile(
                        "mma.sync.aligned.m16n8k8.row.col.f32.tf32.tf32.f32 "
                        "{%0,%1,%2,%3}, {%4,%5,%6,%7}, {%8,%9}, {%0,%1,%2,%3};"
                        : "+f"(acc[mt][nt][0]), "+f"(acc[mt][nt][1]),
                          "+f"(acc[mt][nt][2]), "+f"(acc[mt][nt][3])
                        : "r"(af[mt][0]), "r"(af[mt][1]), "r"(af[mt][2]), "r"(af[mt][3]),
                          "r"(bf[nt][0]), "r"(bf[nt][1]));
        }
        buf ^= 1;
    }

    #pragma unroll
    for (int mt = 0; mt < 4; mt++) {
        #pragma unroll
        for (int half = 0; half < 2; half++) {
            int r = mBase + wM + mt * 16 + g + half * 8;
            if (r < Mloc) {
                #pragma unroll
                for (int nt = 0; nt < 2; nt++) {
                    int col = nBase + wN + nt * 8 + 2 * t;
                    float* cp = C + (size_t)r * N + col;
                    float v0 = acc[mt][nt][half * 2 + 0] + bias[col];
                    float v1 = acc[mt][nt][half * 2 + 1] + bias[col + 1];
                    if (RELU) {
                        v0 = roundtf(fmaxf(v0, 0.0f));
                        v1 = roundtf(fmaxf(v1, 0.0f));
                    }
                    if (ACCUM) { cp[0] += v0; cp[1] += v1; }
                    else       { cp[0] = v0;  cp[1] = v1; }
                }
            }
        }
    }
}

// ---------------- TF32 tensor-core GEMM, 128x128 tile ----------------
#define LDB2 136

template<int RELU, int ACCUM, int EXPERT, int GATHER, int QKV>
__global__ void __launch_bounds__(256)
tgemm2(const float* __restrict__ A,
       const float* __restrict__ W0, const float* __restrict__ Wx1, const float* __restrict__ Wx2,
       const float* __restrict__ B0, const float* __restrict__ Bx1, const float* __restrict__ Bx2,
       float* __restrict__ C0, float* __restrict__ Cx1, float* __restrict__ Cx2,
       int M, int N, int K,
       const int* __restrict__ gather, const int* __restrict__ cnt,
       size_t aStride, size_t cStride)
{
    __shared__ __align__(16) unsigned As[2][128 * LDA];
    __shared__ __align__(16) unsigned Bs[2][16 * LDB2];

    int e = EXPERT ? blockIdx.z : 0;
    int Mloc = EXPERT ? cnt[e] : M;
    int mBase = blockIdx.y * 128;
    if (mBase >= Mloc) return;
    int nBase = blockIdx.x * 128;

    const float* W = W0; const float* bias = B0; float* C = C0;
    if (QKV) {
        int z = blockIdx.z;
        if (z == 1)      { W = Wx1; bias = Bx1; C = Cx1; }
        else if (z == 2) { W = Wx2; bias = Bx2; C = Cx2; }
    }
    const float* Ap = A;
    if (EXPERT) {
        W = W0 + (size_t)e * K * N;
        bias = B0 + (size_t)e * N;
        C = C0 + (size_t)e * cStride;
        if (!GATHER) Ap = A + (size_t)e * aStride;
    }

    int tid = threadIdx.x;
    int lane = tid & 31, warp = tid >> 5;
    int wM = (warp & 1) * 64;       // 2 warps over M
    int wN = (warp >> 1) * 32;      // 4 warps over N
    int g = lane >> 2, t = lane & 3;

    int r0 = tid >> 2;
    int r1 = r0 + 64;
    int ac4 = (tid & 3) * 4;
    int m0 = mBase + r0; m0 = m0 < Mloc ? m0 : Mloc - 1;
    int m1 = mBase + r1; m1 = m1 < Mloc ? m1 : Mloc - 1;
    int ar0 = GATHER ? gather[e * MAXM + m0] : m0;
    int ar1 = GATHER ? gather[e * MAXM + m1] : m1;
    const float* pA0 = Ap + (size_t)ar0 * K + ac4;
    const float* pA1 = Ap + (size_t)ar1 * K + ac4;

    int br  = tid >> 4;
    int bc  = (tid & 15) * 4;
    const float* pB = W + (size_t)br * N + nBase + bc;

    float acc[4][4][4];
    #pragma unroll
    for (int i = 0; i < 4; i++)
        #pragma unroll
        for (int j = 0; j < 4; j++)
            #pragma unroll
            for (int q = 0; q < 4; q++) acc[i][j][q] = 0.0f;

    float4 sa0 = *(const float4*)pA0;
    float4 sa1 = *(const float4*)pA1;
    float4 sb0 = *(const float4*)pB;
    float4 sb1 = *(const float4*)(pB + 64);

    int buf = 0;
    for (int k0 = 0; k0 < K; k0 += 16) {
        unsigned* As_ = As[buf];
        unsigned* Bs_ = Bs[buf];
        *(uint4*)&As_[r0 * LDA + ac4] = *reinterpret_cast<uint4*>(&sa0);
        *(uint4*)&As_[r1 * LDA + ac4] = *reinterpret_cast<uint4*>(&sa1);
        uint4 ub0, ub1;
        ub0.x = f2tf(sb0.x); ub0.y = f2tf(sb0.y); ub0.z = f2tf(sb0.z); ub0.w = f2tf(sb0.w);
        ub1.x = f2tf(sb1.x); ub1.y = f2tf(sb1.y); ub1.z = f2tf(sb1.z); ub1.w = f2tf(sb1.w);
        *(uint4*)&Bs_[br * LDB2 + bc] = ub0;
        *(uint4*)&Bs_[br * LDB2 + bc + 64] = ub1;
        __syncthreads();

        if (k0 + 16 < K) {
            sa0 = *(const float4*)(pA0 + k0 + 16);
            sa1 = *(const float4*)(pA1 + k0 + 16);
            sb0 = *(const float4*)(pB + (size_t)(k0 + 16) * N);
            sb1 = *(const float4*)(pB + (size_t)(k0 + 16) * N + 64);
        }

        #pragma unroll
        for (int ks = 0; ks < 2; ks++) {
            unsigned af[4][4], bf[4][2];
            #pragma unroll
            for (int mt = 0; mt < 4; mt++) {
                int base = (wM + mt * 16 + g) * LDA + ks * 8 + t;
                af[mt][0] = As_[base];
                af[mt][1] = As_[base + 8 * LDA];
                af[mt][2] = As_[base + 4];
                af[mt][3] = As_[base + 8 * LDA + 4];
            }
            #pragma unroll
            for (int nt = 0; nt < 4; nt++) {
                int base = (ks * 8 + t) * LDB2 + wN + nt * 8 + g;
                bf[nt][0] = Bs_[base];
                bf[nt][1] = Bs_[base + 4 * LDB2];
            }
            #pragma unroll
            for (int mt = 0; mt < 4; mt++)
                #pragma unroll
                for (int nt = 0; nt < 4; nt++)
                    asm volatile(
                        "mma.sync.aligned.m16n8k8.row.col.f32.tf32.tf32.f32 "
                        "{%0,%1,%2,%3}, {%4,%5,%6,%7}, {%8,%9}, {%0,%1,%2,%3};"
                        : "+f"(acc[mt][nt][0]), "+f"(acc[mt][nt][1]),
                          "+f"(acc[mt][nt][2]), "+f"(acc[mt][nt][3])
                        : "r"(af[mt][0]), "r"(af[mt][1]), "r"(af[mt][2]), "r"(af[mt][3]),
                          "r"(bf[nt][0]), "r"(bf[nt][1]));
        }
        buf ^= 1;
    }

    #pragma unroll
    for (int mt = 0; mt < 4; mt++) {
        #pragma unroll
        for (int half = 0; half < 2; half++) {
            int r = mBase + wM + mt * 16 + g + half * 8;
            if (r < Mloc) {
                #pragma unroll
                for (int nt = 0; nt < 4; nt++) {
                    int col = nBase + wN + nt * 8 + 2 * t;
                    float* cp = C + (size_t)r * N + col;
                    float v0 = acc[mt][nt][half * 2 + 0] + bias[col];
                    float v1 = acc[mt][nt][half * 2 + 1] + bias[col + 1];
                    if (RELU) {
                        v0 = roundtf(fmaxf(v0, 0.0f));
                        v1 = roundtf(fmaxf(v1, 0.0f));
                    }
                    if (ACCUM) { cp[0] += v0; cp[1] += v1; }
                    else       { cp[0] = v0;  cp[1] = v1; }
                }
            }
        }
    }
}

// ---------------- flash attention, cp.async K/V pipeline ----------------
// Same math/thread mapping as attn4 (bitwise-identical output). K and V live in
// separate smem buffers; V-load overlaps the score phase (wait_group<=1 for K),
// next-K overlaps PV. 3 syncs per tile, no staging registers.
#define QT 32
#define KT 64
#define KVP 68                 // K/V & Q smem row pitch (floats)
#define PP 72                  // P smem row pitch (floats)
#define ATTN5_SMEM ((QT*KVP + 2*KT*KVP + QT*PP) * 4)

__global__ void __launch_bounds__(256)
attn5_kernel(const float* __restrict__ q, const float* __restrict__ k,
             const float* __restrict__ v, const int* __restrict__ abt,
             const float* __restrict__ bias_emb, float* __restrict__ o)
{
    extern __shared__ float sm5[];
    float* Qs = sm5;
    float* Ks = Qs + QT * KVP;
    float* Vs = Ks + KT * KVP;
    float* Ps = Vs + KT * KVP;

    int bid = blockIdx.x;
    int qt = bid & 7, h = (bid >> 3) & 15, b = bid >> 7;
    int q0 = qt * QT;
    int t = threadIdx.x;
    int qpair = t >> 4;
    int q2 = qpair * 2;
    int kk = t & 15;
    int sub = t & 7, vhalf = (t >> 3) & 1;

    // tile-staging geometry: r = t>>2 (0..63), c = (t&3)*16
    int sr = t >> 2, sc = (t & 3) * 16;
    const float* kbase = k + (size_t)(b * SEQ + sr) * DMODEL + h * HDIM + sc;
    const float* vbase = v + (size_t)(b * SEQ + sr) * DMODEL + h * HDIM + sc;
    float* kdst = Ks + sr * KVP + sc;
    float* vdst = Vs + sr * KVP + sc;

    // prologue: async K0, V0
    cpa16(kdst,      kbase);
    cpa16(kdst + 4,  kbase + 4);
    cpa16(kdst + 8,  kbase + 8);
    cpa16(kdst + 12, kbase + 12);
    cp_commit();
    cpa16(vdst,      vbase);
    cpa16(vdst + 4,  vbase + 4);
    cpa16(vdst + 8,  vbase + 8);
    cpa16(vdst + 12, vbase + 12);
    cp_commit();

    // Q tile (scaled by 1/8)
    {
        int r = t >> 3, c = (t & 7) * 8;
        const float* qg = q + (size_t)(b * SEQ + q0 + r) * DMODEL + h * HDIM + c;
        float4 a0 = *(const float4*)qg;
        float4 a1 = *(const float4*)(qg + 4);
        float* dst = Qs + r * KVP + c;
        dst[0] = a0.x * 0.125f; dst[1] = a0.y * 0.125f; dst[2] = a0.z * 0.125f; dst[3] = a0.w * 0.125f;
        dst[4] = a1.x * 0.125f; dst[5] = a1.y * 0.125f; dst[6] = a1.z * 0.125f; dst[7] = a1.w * 0.125f;
    }

    float m0r = -3.4e38f, m1r = -3.4e38f, l0r = 0.0f, l1r = 0.0f;
    float4 oA0 = make_float4(0, 0, 0, 0), oA1 = make_float4(0, 0, 0, 0);
    float4 oB0 = make_float4(0, 0, 0, 0), oB1 = make_float4(0, 0, 0, 0);

    for (int kt = 0; kt < 4; kt++) {
        int k0 = kt * KT;
        cp_wait<1>();          // K_kt complete (V_kt may still be in flight)
        __syncthreads();

        // scores: 2 queries x 4 keys (j = kk + 16*jj)
        float acc0[4] = {0, 0, 0, 0}, acc1[4] = {0, 0, 0, 0};
        const float* qrow0 = Qs + q2 * KVP;
        const float* qrow1 = qrow0 + KVP;
        #pragma unroll
        for (int d4 = 0; d4 < 16; d4++) {
            float4 qa = *(const float4*)(qrow0 + d4 * 4);
            float4 qb = *(const float4*)(qrow1 + d4 * 4);
            #pragma unroll
            for (int jj = 0; jj < 4; jj++) {
                float4 kv = *(const float4*)(Ks + (kk + 16 * jj) * KVP + d4 * 4);
                acc0[jj] += qa.x * kv.x + qa.y * kv.y + qa.z * kv.z + qa.w * kv.w;
                acc1[jj] += qb.x * kv.x + qb.y * kv.y + qb.z * kv.z + qb.w * kv.w;
            }
        }
        const int* arow0 = abt + (size_t)(b * SEQ + q0 + q2) * SEQ + k0;
        const int* arow1 = arow0 + SEQ;
        float tm0 = -3.4e38f, tm1 = -3.4e38f;
        #pragma unroll
        for (int jj = 0; jj < 4; jj++) {
            acc0[jj] += bias_emb[arow0[kk + 16 * jj] * NH + h];
            acc1[jj] += bias_emb[arow1[kk + 16 * jj] * NH + h];
            tm0 = fmaxf(tm0, acc0[jj]);
            tm1 = fmaxf(tm1, acc1[jj]);
        }
        #pragma unroll
        for (int off = 8; off > 0; off >>= 1) {
            tm0 = fmaxf(tm0, __shfl_xor_sync(0xffffffffu, tm0, off));
            tm1 = fmaxf(tm1, __shfl_xor_sync(0xffffffffu, tm1, off));
        }
        float mn0 = fmaxf(m0r, tm0), mn1 = fmaxf(m1r, tm1);
        float a0 = expf(m0r - mn0), a1 = expf(m1r - mn1);
        float ts0 = 0.0f, ts1 = 0.0f;
        #pragma unroll
        for (int jj = 0; jj < 4; jj++) {
            float p0 = expf(acc0[jj] - mn0);
            float p1 = expf(acc1[jj] - mn1);
            Ps[q2 * PP + kk + 16 * jj] = p0;
            Ps[(q2 + 1) * PP + kk + 16 * jj] = p1;
            ts0 += p0; ts1 += p1;
        }
        #pragma unroll
        for (int off = 8; off > 0; off >>= 1) {
            ts0 += __shfl_xor_sync(0xffffffffu, ts0, off);
            ts1 += __shfl_xor_sync(0xffffffffu, ts1, off);
        }
        l0r = l0r * a0 + ts0; m0r = mn0;
        l1r = l1r * a1 + ts1; m1r = mn1;

        cp_wait<0>();          // V_kt complete
        __syncthreads();       // Ps visible; score reads of Ks done

        // prefetch next K (overlaps PV)
        if (kt < 3) {
            const float* kn = kbase + (size_t)(k0 + KT) * DMODEL;
            cpa16(kdst,      kn);
            cpa16(kdst + 4,  kn + 4);
            cpa16(kdst + 8,  kn + 8);
            cpa16(kdst + 12, kn + 12);
            cp_commit();
        }

        // PV accumulate: this thread covers keys [vhalf*32, vhalf*32+32)
        oA0.x *= a0; oA0.y *= a0; oA0.z *= a0; oA0.w *= a0;
        oA1.x *= a0; oA1.y *= a0; oA1.z *= a0; oA1.w *= a0;
        oB0.x *= a1; oB0.y *= a1; oB0.z *= a1; oB0.w *= a1;
        oB1.x *= a1; oB1.y *= a1; oB1.z *= a1; oB1.w *= a1;
        const float* p0 = Ps + q2 * PP + vhalf * 32;
        const float* p1 = p0 + PP;
        #pragma unroll
        for (int j4 = 0; j4 < 8; j4++) {
            float4 pa = *(const float4*)(p0 + j4 * 4);
            float4 pb = *(const float4*)(p1 + j4 * 4);
            float par[4] = {pa.x, pa.y, pa.z, pa.w};
            float pbr[4] = {pb.x, pb.y, pb.z, pb.w};
            #pragma unroll
            for (int u = 0; u < 4; u++) {
                int j = vhalf * 32 + j4 * 4 + u;
                float4 va = *(const float4*)(Vs + j * KVP + sub * 4);
                float4 vb = *(const float4*)(Vs + j * KVP + (sub + 8) * 4);
                float pA = par[u], pB = pbr[u];
                oA0.x += pA * va.x; oA0.y += pA * va.y; oA0.z += pA * va.z; oA0.w += pA * va.w;
                oA1.x += pA * vb.x; oA1.y += pA * vb.y; oA1.z += pA * vb.z; oA1.w += pA * vb.w;
                oB0.x += pB * va.x; oB0.y += pB * va.y; oB0.z += pB * va.z; oB0.w += pB * va.w;
                oB1.x += pB * vb.x; oB1.y += pB * vb.y; oB1.z += pB * vb.z; oB1.w += pB * vb.w;
            }
        }
        __syncthreads();       // PV reads of Vs/Ps done

        // prefetch next V (overlaps next tile's score phase)
        if (kt < 3) {
            const float* vn = vbase + (size_t)(k0 + KT) * DMODEL;
            cpa16(vdst,      vn);
            cpa16(vdst + 4,  vn + 4);
            cpa16(vdst + 8,  vn + 8);
            cpa16(vdst + 12, vn + 12);
            cp_commit();
        }
    }

    #pragma unroll
    for (int c = 0; c < 4; c++) {
        ((float*)&oA0)[c] += __shfl_xor_sync(0xffffffffu, ((float*)&oA0)[c], 8);
        ((float*)&oA1)[c] += __shfl_xor_sync(0xffffffffu, ((float*)&oA1)[c], 8);
        ((float*)&oB0)[c] += __shfl_xor_sync(0xffffffffu, ((float*)&oB0)[c], 8);
        ((float*)&oB1)[c] += __shfl_xor_sync(0xffffffffu, ((float*)&oB1)[c], 8);
    }

    float invq = (vhalf == 0) ? (1.0f / l0r) : (1.0f / l1r);
    float4 w0 = (vhalf == 0) ? oA0 : oB0;
    float4 w1 = (vhalf == 0) ? oA1 : oB1;
    w0.x = roundtf(w0.x * invq); w0.y = roundtf(w0.y * invq);
    w0.z = roundtf(w0.z * invq); w0.w = roundtf(w0.w * invq);
    w1.x = roundtf(w1.x * invq); w1.y = roundtf(w1.y * invq);
    w1.z = roundtf(w1.z * invq); w1.w = roundtf(w1.w * invq);
    float* og = o + (size_t)(b * SEQ + q0 + q2 + vhalf) * DMODEL + h * HDIM;
    *(float4*)(og + sub * 4) = w0;
    *(float4*)(og + 32 + sub * 4) = w1;
}

// ---------------- host orchestration ----------------
extern "C" void kernel_launch(void* const* d_in, const int* in_sizes, int n_in,
                              void* d_out, int out_size)
{
    (void)in_sizes; (void)n_in; (void)out_size;
    const int*   et       = (const int*)d_in[0];
    const int*   xi       = (const int*)d_in[1];
    const int*   abt      = (const int*)d_in[2];
    const float* ent      = (const float*)d_in[3];
    const float* maskemb  = (const float*)d_in[4];
    const float* rel      = (const float*)d_in[5];
    const float* type     = (const float*)d_in[6];
    const float* bias_emb = (const float*)d_in[7];
    const float* ln1g     = (const float*)d_in[8];
    const float* ln1b     = (const float*)d_in[9];
    const float* wq       = (const float*)d_in[10];
    const float* bq       = (const float*)d_in[11];
    const float* wk       = (const float*)d_in[12];
    const float* bk       = (const float*)d_in[13];
    const float* wv       = (const float*)d_in[14];
    const float* bv       = (const float*)d_in[15];
    const float* wo       = (const float*)d_in[16];
    const float* bo       = (const float*)d_in[17];
    const float* ln2g     = (const float*)d_in[18];
    const float* ln2b     = (const float*)d_in[19];
    const float* gw       = (const float*)d_in[20];
    const float* gb       = (const float*)d_in[21];
    const float* w1       = (const float*)d_in[22];
    const float* b1       = (const float*)d_in[23];
    const float* w2       = (const float*)d_in[24];
    const float* b2       = (const float*)d_in[25];
    const float* flng     = (const float*)d_in[26];
    const float* flnb     = (const float*)d_in[27];
    float* out = (float*)d_out;

    float *feat, *xnr, *qb2, *kb2, *vb2, *ob, *hb, *yb;
    int *cntp, *ptokp;
    cudaGetSymbolAddress((void**)&feat,  g_feat);
    cudaGetSymbolAddress((void**)&xnr,   g_xnr);
    cudaGetSymbolAddress((void**)&qb2,   g_q);
    cudaGetSymbolAddress((void**)&kb2,   g_k);
    cudaGetSymbolAddress((void**)&vb2,   g_v);
    cudaGetSymbolAddress((void**)&ob,    g_o);
    cudaGetSymbolAddress((void**)&hb,    g_h);
    cudaGetSymbolAddress((void**)&yb,    g_y2);
    cudaGetSymbolAddress((void**)&cntp,  g_cnt);
    cudaGetSymbolAddress((void**)&ptokp, g_ptok);

    static int attr_set = 0;
    if (!attr_set) {
        cudaFuncSetAttribute(attn5_kernel,
                             cudaFuncAttributeMaxDynamicSharedMemorySize, ATTN5_SMEM);
        attr_set = 1;
    }

    for (int l = 0; l < 2; l++) {
        const size_t dd = (size_t)DMODEL * DMODEL;
        // 1) LN1: layer 0 fuses the embedding; layer 1 fuses the MoE combine.
        //    Both clear g_cnt for this layer's routing.
        if (l == 0)
            embed_ln_kernel<<<NTOK, 256>>>(et, xi, ent, maskemb, rel, type,
                                           ln1g, ln1b, xnr);
        else
            lnf_kernel<1,0,0,1><<<NTOK, 256>>>(feat, ln1g + l * DMODEL, ln1b + l * DMODEL, xnr,
                                               (const float*)0, (const float*)0);
        // 2) fused q,k,v projections (128x128 tiles)
        tgemm2<0,0,0,0,1><<<dim3(8, 8, 3), 256>>>(
            xnr, wq + l * dd, wk + l * dd, wv + l * dd,
            bq + l * DMODEL, bk + l * DMODEL, bv + l * DMODEL,
            qb2, kb2, vb2,
            NTOK, DMODEL, DMODEL, (const int*)0, (const int*)0, 0, 0);
        // 3) attention (flash, cp.async K/V pipeline); output pre-rounded
        attn5_kernel<<<NB * NH * (SEQ / QT), 256, ATTN5_SMEM>>>(
            qb2, kb2, vb2, abt, bias_emb, ob);
        // 4) out proj + residual accumulate (64-wide tiles)
        tgemm<0,1,0,0,0><<<dim3(16, 8), 256>>>(
            ob, wo + l * dd, (const float*)0, (const float*)0,
            bo + l * DMODEL, (const float*)0, (const float*)0,
            feat, (float*)0, (float*)0,
            NTOK, DMODEL, DMODEL, (const int*)0, (const int*)0, 0, 0);
        // 5) LN2 + fused routing -> xnr, g_pos/g_wgt/g_ptok/g_cnt
        lnf_kernel<0,1,0,0><<<NTOK, 256>>>(feat, ln2g + l * DMODEL, ln2b + l * DMODEL, xnr,
                                           gw + (size_t)l * DMODEL * NE, gb + l * NE);
        // 6) expert up-proj + relu (gathered rows of xnr); output pre-rounded
        tgemm2<1,0,1,1,0><<<dim3(16, 8, 8), 256>>>(
            xnr, w1 + (size_t)l * NE * DMODEL * DHID, (const float*)0, (const float*)0,
            b1 + (size_t)l * NE * DHID, (const float*)0, (const float*)0,
            hb, (float*)0, (float*)0,
            MAXM, DHID, DMODEL, ptokp, cntp, 0, (size_t)MAXM * DHID);
        // 7) expert down-proj
        tgemm2<0,0,1,0,0><<<dim3(8, 8, 8), 256>>>(
            hb, w2 + (size_t)l * NE * DHID * DMODEL, (const float*)0, (const float*)0,
            b2 + (size_t)l * NE * DMODEL, (const float*)0, (const float*)0,
            yb, (float*)0, (float*)0,
            MAXM, DMODEL, DHID, (const int*)0, cntp, (size_t)MAXM * DHID, (size_t)MAXM * DMODEL);
    }

    // final layernorm (+combine of layer-1 MoE) -> exact out
    lnf_kernel<1,0,1,0><<<NTOK, 256>>>(feat, flng, flnb, out,
                                       (const float*)0, (const float*)0);
}